// round 2
// baseline (speedup 1.0000x reference)
#include <cuda_runtime.h>

#define BATCH 2
#define SEQ 2048
#define DMODEL 1024
#define NH 16
#define HD 64
#define BH (BATCH * NH)
#define N_QKV (3 * DMODEL)

// Scratch (allocation-free): Q/K/V in [bh, s, hd] layout, attention output in [b, s, d]
__device__ float g_q[BH * SEQ * HD];
__device__ float g_k[BH * SEQ * HD];
__device__ float g_v[BH * SEQ * HD];
__device__ float g_att[BATCH * SEQ * DMODEL];

// ---------------------------------------------------------------------------
// Kernel 1: QKV GEMM  C[4096,3072] = X[4096,1024] @ W_qkv + b_qkv,
// epilogue scatters into g_q/g_k/g_v with [bh, s, hd] layout.
// 64x64 block tile, BK=16, 256 threads, 4x4 per-thread micro-tile.
// ---------------------------------------------------------------------------
__global__ __launch_bounds__(256) void qkv_gemm_kernel(
    const float* __restrict__ X, const float* __restrict__ W,
    const float* __restrict__ bias)
{
    __shared__ float As[64][17];   // [m][k]
    __shared__ float Ws[16][65];   // [k][n]

    const int tid = threadIdx.x;
    const int tx = tid & 15, ty = tid >> 4;
    const int m0 = blockIdx.y * 64;
    const int n0 = blockIdx.x * 64;

    const int ar = tid >> 2;          // 0..63 (A row in tile)
    const int ak = (tid & 3) * 4;     // 0,4,8,12
    const int wk = tid >> 4;          // 0..15
    const int wn = (tid & 15) * 4;    // 0..60

    float acc[4][4] = {};

    for (int kt = 0; kt < DMODEL; kt += 16) {
        float4 av = *reinterpret_cast<const float4*>(&X[(m0 + ar) * DMODEL + kt + ak]);
        float4 wv = *reinterpret_cast<const float4*>(&W[(kt + wk) * N_QKV + n0 + wn]);
        __syncthreads();
        As[ar][ak + 0] = av.x; As[ar][ak + 1] = av.y;
        As[ar][ak + 2] = av.z; As[ar][ak + 3] = av.w;
        Ws[wk][wn + 0] = wv.x; Ws[wk][wn + 1] = wv.y;
        Ws[wk][wn + 2] = wv.z; Ws[wk][wn + 3] = wv.w;
        __syncthreads();
        #pragma unroll
        for (int kk = 0; kk < 16; kk++) {
            float a[4], w[4];
            #pragma unroll
            for (int i = 0; i < 4; i++) a[i] = As[ty + 16 * i][kk];
            #pragma unroll
            for (int j = 0; j < 4; j++) w[j] = Ws[kk][tx + 16 * j];
            #pragma unroll
            for (int i = 0; i < 4; i++)
                #pragma unroll
                for (int j = 0; j < 4; j++)
                    acc[i][j] += a[i] * w[j];
        }
    }

    #pragma unroll
    for (int i = 0; i < 4; i++) {
        const int m = m0 + ty + 16 * i;
        const int b = m >> 11;        // / SEQ
        const int s = m & (SEQ - 1);
        #pragma unroll
        for (int j = 0; j < 4; j++) {
            const int n = n0 + tx + 16 * j;
            const float v = acc[i][j] + bias[n];
            const int h = n / 192;
            const int r = n - h * 192;
            const int which = r >> 6;
            const int d = r & 63;
            const int idx = ((b * NH + h) * SEQ + s) * HD + d;
            if (which == 0)      g_q[idx] = v;
            else if (which == 1) g_k[idx] = v;
            else                 g_v[idx] = v;
        }
    }
}

// ---------------------------------------------------------------------------
// Kernel 2: causal flash attention per (bh, q-tile of 64 rows).
// 64x64 S/P tiles, online softmax, only tiles kt <= qt are visited.
// Smem: Qs (swizzled), KP (K then reused for P, swizzled), Vs (natural).
// ---------------------------------------------------------------------------
__global__ __launch_bounds__(256) void attn_kernel()
{
    __shared__ float Qs[64 * 64];
    __shared__ float KP[64 * 64];
    __shared__ float Vs[64 * 64];

    const int tid = threadIdx.x;
    const int tx = tid & 15, ty = tid >> 4;
    const int qt = blockIdx.x;
    const int bh = blockIdx.y;
    const int qbase = qt * 64;

    const float* __restrict__ Qg = g_q + (size_t)bh * SEQ * HD + (size_t)qbase * HD;
    const float* __restrict__ Kg = g_k + (size_t)bh * SEQ * HD;
    const float* __restrict__ Vg = g_v + (size_t)bh * SEQ * HD;

    const int lr = tid >> 4;          // 0..15
    const int ld = (tid & 15) * 4;    // 0..60

    // Load Q tile (pre-scaled by 1/sqrt(HD) = 0.125), XOR-swizzled rows
    #pragma unroll
    for (int it = 0; it < 4; it++) {
        const int r = lr + 16 * it;
        float4 v = *reinterpret_cast<const float4*>(&Qg[r * HD + ld]);
        const int sw = r & 31;
        Qs[r * 64 + ((ld + 0) ^ sw)] = v.x * 0.125f;
        Qs[r * 64 + ((ld + 1) ^ sw)] = v.y * 0.125f;
        Qs[r * 64 + ((ld + 2) ^ sw)] = v.z * 0.125f;
        Qs[r * 64 + ((ld + 3) ^ sw)] = v.w * 0.125f;
    }

    float m_i[4], l_i[4], acc[4][4];
    #pragma unroll
    for (int i = 0; i < 4; i++) {
        m_i[i] = -1e30f; l_i[i] = 0.0f;
        #pragma unroll
        for (int j = 0; j < 4; j++) acc[i][j] = 0.0f;
    }

    for (int kt2 = 0; kt2 <= qt; kt2++) {
        const int kbase = kt2 * 64;
        __syncthreads();   // previous PV done reading KP/Vs; Q visible on iter 0
        #pragma unroll
        for (int it = 0; it < 4; it++) {
            const int r = lr + 16 * it;
            float4 kv = *reinterpret_cast<const float4*>(&Kg[(size_t)(kbase + r) * HD + ld]);
            const int sw = r & 31;
            KP[r * 64 + ((ld + 0) ^ sw)] = kv.x;
            KP[r * 64 + ((ld + 1) ^ sw)] = kv.y;
            KP[r * 64 + ((ld + 2) ^ sw)] = kv.z;
            KP[r * 64 + ((ld + 3) ^ sw)] = kv.w;
            float4 vv = *reinterpret_cast<const float4*>(&Vg[(size_t)(kbase + r) * HD + ld]);
            *reinterpret_cast<float4*>(&Vs[r * 64 + ld]) = vv;
        }
        __syncthreads();

        // S = Q K^T (Q pre-scaled)
        float s[4][4] = {};
        #pragma unroll 8
        for (int k = 0; k < 64; k++) {
            float qv[4], kv[4];
            #pragma unroll
            for (int i = 0; i < 4; i++) {
                const int r = ty + 16 * i;
                qv[i] = Qs[r * 64 + (k ^ (r & 31))];
            }
            #pragma unroll
            for (int j = 0; j < 4; j++) {
                const int c = tx + 16 * j;
                kv[j] = KP[c * 64 + (k ^ (c & 31))];
            }
            #pragma unroll
            for (int i = 0; i < 4; i++)
                #pragma unroll
                for (int j = 0; j < 4; j++)
                    s[i][j] += qv[i] * kv[j];
        }

        // causal mask only on diagonal tile: key kbase+c > query qbase+r  <=>  c > r
        if (kt2 == qt) {
            #pragma unroll
            for (int i = 0; i < 4; i++)
                #pragma unroll
                for (int j = 0; j < 4; j++)
                    if (tx + 16 * j > ty + 16 * i) s[i][j] = -1e30f;
        }

        __syncthreads();   // all K reads done before P overwrites KP

        // online softmax (row reductions over 16 lanes sharing ty)
        float p[4][4];
        #pragma unroll
        for (int i = 0; i < 4; i++) {
            float rm = s[i][0];
            #pragma unroll
            for (int j = 1; j < 4; j++) rm = fmaxf(rm, s[i][j]);
            #pragma unroll
            for (int o = 8; o >= 1; o >>= 1)
                rm = fmaxf(rm, __shfl_xor_sync(0xffffffffu, rm, o));
            const float mnew = fmaxf(m_i[i], rm);
            const float corr = __expf(m_i[i] - mnew);
            float rs = 0.0f;
            #pragma unroll
            for (int j = 0; j < 4; j++) {
                p[i][j] = __expf(s[i][j] - mnew);
                rs += p[i][j];
            }
            #pragma unroll
            for (int o = 8; o >= 1; o >>= 1)
                rs += __shfl_xor_sync(0xffffffffu, rs, o);
            l_i[i] = l_i[i] * corr + rs;
            m_i[i] = mnew;
            #pragma unroll
            for (int j = 0; j < 4; j++) acc[i][j] *= corr;
        }

        // store P into KP (swizzled by row)
        #pragma unroll
        for (int i = 0; i < 4; i++) {
            const int r = ty + 16 * i;
            const int sw = r & 31;
            #pragma unroll
            for (int j = 0; j < 4; j++) {
                const int c = tx + 16 * j;
                KP[r * 64 + (c ^ sw)] = p[i][j];
            }
        }
        __syncthreads();

        // O += P @ V
        #pragma unroll 8
        for (int k = 0; k < 64; k++) {
            float pv[4], vv[4];
            #pragma unroll
            for (int i = 0; i < 4; i++) {
                const int r = ty + 16 * i;
                pv[i] = KP[r * 64 + (k ^ (r & 31))];
            }
            #pragma unroll
            for (int j = 0; j < 4; j++) vv[j] = Vs[k * 64 + tx + 16 * j];
            #pragma unroll
            for (int i = 0; i < 4; i++)
                #pragma unroll
                for (int j = 0; j < 4; j++)
                    acc[i][j] += pv[i] * vv[j];
        }
    }

    // write normalized output, back to [b, s, h*HD + d]
    const int b = bh >> 4, h = bh & 15;
    #pragma unroll
    for (int i = 0; i < 4; i++) {
        const int r = ty + 16 * i;
        const float inv = 1.0f / l_i[i];
        const int srow = qbase + r;
        #pragma unroll
        for (int j = 0; j < 4; j++) {
            const int d = tx + 16 * j;
            g_att[(size_t)(b * SEQ + srow) * DMODEL + h * HD + d] = acc[i][j] * inv;
        }
    }
}

// ---------------------------------------------------------------------------
// Kernel 3: output GEMM  out[4096,1024] = g_att @ W_o + b_o
// ---------------------------------------------------------------------------
__global__ __launch_bounds__(256) void out_gemm_kernel(
    const float* __restrict__ W, const float* __restrict__ bias,
    float* __restrict__ out)
{
    __shared__ float As[64][17];
    __shared__ float Ws[16][65];

    const int tid = threadIdx.x;
    const int tx = tid & 15, ty = tid >> 4;
    const int m0 = blockIdx.y * 64;
    const int n0 = blockIdx.x * 64;

    const int ar = tid >> 2;
    const int ak = (tid & 3) * 4;
    const int wk = tid >> 4;
    const int wn = (tid & 15) * 4;

    float acc[4][4] = {};

    for (int kt = 0; kt < DMODEL; kt += 16) {
        float4 av = *reinterpret_cast<const float4*>(&g_att[(m0 + ar) * DMODEL + kt + ak]);
        float4 wv = *reinterpret_cast<const float4*>(&W[(kt + wk) * DMODEL + n0 + wn]);
        __syncthreads();
        As[ar][ak + 0] = av.x; As[ar][ak + 1] = av.y;
        As[ar][ak + 2] = av.z; As[ar][ak + 3] = av.w;
        Ws[wk][wn + 0] = wv.x; Ws[wk][wn + 1] = wv.y;
        Ws[wk][wn + 2] = wv.z; Ws[wk][wn + 3] = wv.w;
        __syncthreads();
        #pragma unroll
        for (int kk = 0; kk < 16; kk++) {
            float a[4], w[4];
            #pragma unroll
            for (int i = 0; i < 4; i++) a[i] = As[ty + 16 * i][kk];
            #pragma unroll
            for (int j = 0; j < 4; j++) w[j] = Ws[kk][tx + 16 * j];
            #pragma unroll
            for (int i = 0; i < 4; i++)
                #pragma unroll
                for (int j = 0; j < 4; j++)
                    acc[i][j] += a[i] * w[j];
        }
    }

    #pragma unroll
    for (int i = 0; i < 4; i++) {
        const int m = m0 + ty + 16 * i;
        #pragma unroll
        for (int j = 0; j < 4; j++) {
            const int n = n0 + tx + 16 * j;
            out[m * DMODEL + n] = acc[i][j] + bias[n];
        }
    }
}

// ---------------------------------------------------------------------------
extern "C" void kernel_launch(void* const* d_in, const int* in_sizes, int n_in,
                              void* d_out, int out_size)
{
    const float* x     = (const float*)d_in[0];
    // d_in[1] is the causal mask; causality is implemented directly.
    const float* W_qkv = (const float*)d_in[2];
    const float* b_qkv = (const float*)d_in[3];
    const float* W_o   = (const float*)d_in[4];
    const float* b_o   = (const float*)d_in[5];
    float* out = (float*)d_out;

    qkv_gemm_kernel<<<dim3(N_QKV / 64, (BATCH * SEQ) / 64), 256>>>(x, W_qkv, b_qkv);
    attn_kernel<<<dim3(SEQ / 64, BH), 256>>>();
    out_gemm_kernel<<<dim3(DMODEL / 64, (BATCH * SEQ) / 64), 256>>>(W_o, b_o, out);
}

// round 4
// speedup vs baseline: 1.6896x; 1.6896x over previous
#include <cuda_runtime.h>
#include <cstdint>

#define BATCH 2
#define SEQ 2048
#define DMODEL 1024
#define NH 16
#define HD 64
#define BH (BATCH * NH)
#define N_QKV (3 * DMODEL)
#define GK 1024

// Scratch (allocation-free)
__device__ float g_q[BH * SEQ * HD];
__device__ float g_k[BH * SEQ * HD];
__device__ float g_v[BH * SEQ * HD];
__device__ float g_att[BATCH * SEQ * DMODEL];
__device__ float g_wqkv_t[N_QKV * GK];   // [N=3072, K=1024]
__device__ float g_wo_t[DMODEL * GK];    // [N=1024, K=1024]

__device__ __forceinline__ uint32_t f2tf32(float f) {
    uint32_t u;
    asm("cvt.rna.tf32.f32 %0, %1;" : "=r"(u) : "f"(f));
    return u;
}

__device__ __forceinline__ void mma_tf32(
    float& c0, float& c1, float& c2, float& c3,
    uint32_t a0, uint32_t a1, uint32_t a2, uint32_t a3,
    uint32_t b0, uint32_t b1)
{
    asm volatile(
        "mma.sync.aligned.m16n8k8.row.col.f32.tf32.tf32.f32 "
        "{%0,%1,%2,%3}, {%4,%5,%6,%7}, {%8,%9}, {%0,%1,%2,%3};"
        : "+f"(c0), "+f"(c1), "+f"(c2), "+f"(c3)
        : "r"(a0), "r"(a1), "r"(a2), "r"(a3), "r"(b0), "r"(b1));
}

// ===========================================================================
// Transpose: out[c][r] = in[r][c], in is R x C row-major
// ===========================================================================
__global__ void transpose_kernel(const float* __restrict__ in,
                                 float* __restrict__ out, int R, int C)
{
    __shared__ float t[32][33];
    int c0 = blockIdx.x * 32, r0 = blockIdx.y * 32;
    int x = threadIdx.x, y = threadIdx.y;  // block (32, 8)
    #pragma unroll
    for (int i = 0; i < 32; i += 8)
        t[y + i][x] = in[(size_t)(r0 + y + i) * C + c0 + x];
    __syncthreads();
    #pragma unroll
    for (int i = 0; i < 32; i += 8)
        out[(size_t)(c0 + y + i) * R + r0 + x] = t[x][y + i];
}

// ===========================================================================
// tf32 mma.sync GEMM: C[4096, N] = A[4096,1024] @ Bt^T + bias
//   Bt is [N, 1024] K-major. CTA tile 128x128, 8 warps (4M x 2N), warp 32x64.
//   KC=32 double-buffered. Smem rows padded to 36 floats (bank-perfect frags).
//   EPI 0: scatter into g_q/g_k/g_v.  EPI 1: plain write.
// ===========================================================================
#define KC 32
#define NKC (GK / KC)
#define ROWSTRIDE 36
#define STAGE_U32 (128 * ROWSTRIDE)            // one operand, one stage
#define TC_SMEM_BYTES (4 * STAGE_U32 * 4)      // A0,B0,A1,B1 = 73728 B

template<int EPI>
__global__ __launch_bounds__(256, 2) void tc_gemm_kernel(
    const float* __restrict__ A, const float* __restrict__ Bt,
    const float* __restrict__ bias, float* __restrict__ C)
{
    extern __shared__ uint32_t sm[];
    // layout: [stage][A(4608) | B(4608)]
    const int tid = threadIdx.x;
    const int wid = tid >> 5, lane = tid & 31;
    const int grp = lane >> 2, tig = lane & 3;
    const int wm = wid >> 1, wn = wid & 1;      // 4 x 2 warps
    const int m0 = blockIdx.y * 128;
    const int n0 = blockIdx.x * 128;

    const float* Ag = A + (size_t)m0 * GK;
    const float* Bg = Bt + (size_t)n0 * GK;

    // per-thread global-load coords: 4 float4 per operand per chunk
    const int lr = tid >> 3;          // 0..31 (x4 -> 128 rows)
    const int lc = (tid & 7) * 4;     // 0,4,...,28

    float acc[2][8][4];
    #pragma unroll
    for (int i = 0; i < 2; i++)
        #pragma unroll
        for (int j = 0; j < 8; j++)
            #pragma unroll
            for (int q = 0; q < 4; q++) acc[i][j][q] = 0.0f;

    // ---- load chunk 0 into stage 0 ----
    {
        #pragma unroll
        for (int i = 0; i < 4; i++) {
            const int r = lr + 32 * i;
            float4 av = *reinterpret_cast<const float4*>(Ag + (size_t)r * GK + lc);
            float4 bv = *reinterpret_cast<const float4*>(Bg + (size_t)r * GK + lc);
            uint32_t* as = sm + r * ROWSTRIDE + lc;
            uint32_t* bs = sm + STAGE_U32 + r * ROWSTRIDE + lc;
            as[0] = f2tf32(av.x); as[1] = f2tf32(av.y);
            as[2] = f2tf32(av.z); as[3] = f2tf32(av.w);
            bs[0] = f2tf32(bv.x); bs[1] = f2tf32(bv.y);
            bs[2] = f2tf32(bv.z); bs[3] = f2tf32(bv.w);
        }
    }
    __syncthreads();

    for (int kc = 0; kc < NKC; kc++) {
        const uint32_t* As = sm + (kc & 1) * 2 * STAGE_U32;
        const uint32_t* Bs = As + STAGE_U32;

        // prefetch next chunk to registers
        float4 pav[4], pbv[4];
        if (kc + 1 < NKC) {
            const float* An = Ag + (kc + 1) * KC;
            const float* Bn = Bg + (kc + 1) * KC;
            #pragma unroll
            for (int i = 0; i < 4; i++) {
                const int r = lr + 32 * i;
                pav[i] = *reinterpret_cast<const float4*>(An + (size_t)r * GK + lc);
                pbv[i] = *reinterpret_cast<const float4*>(Bn + (size_t)r * GK + lc);
            }
        }

        // compute: 4 k-steps of 8
        #pragma unroll
        for (int ks = 0; ks < 4; ks++) {
            const int kof = ks * 8;
            uint32_t af[2][4];
            #pragma unroll
            for (int mt = 0; mt < 2; mt++) {
                const int ab = wm * 32 + mt * 16;
                af[mt][0] = As[(ab + grp) * ROWSTRIDE + kof + tig];
                af[mt][1] = As[(ab + grp + 8) * ROWSTRIDE + kof + tig];
                af[mt][2] = As[(ab + grp) * ROWSTRIDE + kof + tig + 4];
                af[mt][3] = As[(ab + grp + 8) * ROWSTRIDE + kof + tig + 4];
            }
            #pragma unroll
            for (int nt = 0; nt < 8; nt++) {
                const int nb = wn * 64 + nt * 8;
                uint32_t b0 = Bs[(nb + grp) * ROWSTRIDE + kof + tig];
                uint32_t b1 = Bs[(nb + grp) * ROWSTRIDE + kof + tig + 4];
                #pragma unroll
                for (int mt = 0; mt < 2; mt++)
                    mma_tf32(acc[mt][nt][0], acc[mt][nt][1],
                             acc[mt][nt][2], acc[mt][nt][3],
                             af[mt][0], af[mt][1], af[mt][2], af[mt][3],
                             b0, b1);
            }
        }
        __syncthreads();

        if (kc + 1 < NKC) {
            uint32_t* dst = sm + ((kc + 1) & 1) * 2 * STAGE_U32;
            #pragma unroll
            for (int i = 0; i < 4; i++) {
                const int r = lr + 32 * i;
                uint32_t* as = dst + r * ROWSTRIDE + lc;
                uint32_t* bs = dst + STAGE_U32 + r * ROWSTRIDE + lc;
                as[0] = f2tf32(pav[i].x); as[1] = f2tf32(pav[i].y);
                as[2] = f2tf32(pav[i].z); as[3] = f2tf32(pav[i].w);
                bs[0] = f2tf32(pbv[i].x); bs[1] = f2tf32(pbv[i].y);
                bs[2] = f2tf32(pbv[i].z); bs[3] = f2tf32(pbv[i].w);
            }
        }
        __syncthreads();
    }

    // ---- epilogue ----
    #pragma unroll
    for (int mt = 0; mt < 2; mt++) {
        #pragma unroll
        for (int half = 0; half < 2; half++) {   // c0/c1 (row grp) vs c2/c3 (row grp+8)
            const int m = m0 + wm * 32 + mt * 16 + grp + half * 8;
            #pragma unroll
            for (int nt = 0; nt < 8; nt++) {
                #pragma unroll
                for (int e = 0; e < 2; e++) {
                    const int n = n0 + wn * 64 + nt * 8 + tig * 2 + e;
                    const float v = acc[mt][nt][half * 2 + e] + __ldg(&bias[n]);
                    if (EPI == 0) {
                        const int b = m >> 11;
                        const int srow = m & (SEQ - 1);
                        const int h = n / 192;
                        const int r = n - h * 192;
                        const int which = r >> 6;
                        const int dd = r & 63;
                        const size_t idx =
                            ((size_t)(b * NH + h) * SEQ + srow) * HD + dd;
                        if (which == 0)      g_q[idx] = v;
                        else if (which == 1) g_k[idx] = v;
                        else                 g_v[idx] = v;
                    } else {
                        C[(size_t)m * DMODEL + n] = v;
                    }
                }
            }
        }
    }
}

// ===========================================================================
// Causal flash attention (unchanged from passing round-2 version)
// ===========================================================================
__global__ __launch_bounds__(256) void attn_kernel()
{
    __shared__ float Qs[64 * 64];
    __shared__ float KP[64 * 64];
    __shared__ float Vs[64 * 64];

    const int tid = threadIdx.x;
    const int tx = tid & 15, ty = tid >> 4;
    const int qt = blockIdx.x;
    const int bh = blockIdx.y;
    const int qbase = qt * 64;

    const float* __restrict__ Qg = g_q + (size_t)bh * SEQ * HD + (size_t)qbase * HD;
    const float* __restrict__ Kg = g_k + (size_t)bh * SEQ * HD;
    const float* __restrict__ Vg = g_v + (size_t)bh * SEQ * HD;

    const int lr = tid >> 4;
    const int ld = (tid & 15) * 4;

    #pragma unroll
    for (int it = 0; it < 4; it++) {
        const int r = lr + 16 * it;
        float4 v = *reinterpret_cast<const float4*>(&Qg[r * HD + ld]);
        const int sw = r & 31;
        Qs[r * 64 + ((ld + 0) ^ sw)] = v.x * 0.125f;
        Qs[r * 64 + ((ld + 1) ^ sw)] = v.y * 0.125f;
        Qs[r * 64 + ((ld + 2) ^ sw)] = v.z * 0.125f;
        Qs[r * 64 + ((ld + 3) ^ sw)] = v.w * 0.125f;
    }

    float m_i[4], l_i[4], acc[4][4];
    #pragma unroll
    for (int i = 0; i < 4; i++) {
        m_i[i] = -1e30f; l_i[i] = 0.0f;
        #pragma unroll
        for (int j = 0; j < 4; j++) acc[i][j] = 0.0f;
    }

    for (int kt2 = 0; kt2 <= qt; kt2++) {
        const int kbase = kt2 * 64;
        __syncthreads();
        #pragma unroll
        for (int it = 0; it < 4; it++) {
            const int r = lr + 16 * it;
            float4 kv = *reinterpret_cast<const float4*>(&Kg[(size_t)(kbase + r) * HD + ld]);
            const int sw = r & 31;
            KP[r * 64 + ((ld + 0) ^ sw)] = kv.x;
            KP[r * 64 + ((ld + 1) ^ sw)] = kv.y;
            KP[r * 64 + ((ld + 2) ^ sw)] = kv.z;
            KP[r * 64 + ((ld + 3) ^ sw)] = kv.w;
            float4 vv = *reinterpret_cast<const float4*>(&Vg[(size_t)(kbase + r) * HD + ld]);
            *reinterpret_cast<float4*>(&Vs[r * 64 + ld]) = vv;
        }
        __syncthreads();

        float s[4][4] = {};
        #pragma unroll 8
        for (int k = 0; k < 64; k++) {
            float qv[4], kv[4];
            #pragma unroll
            for (int i = 0; i < 4; i++) {
                const int r = ty + 16 * i;
                qv[i] = Qs[r * 64 + (k ^ (r & 31))];
            }
            #pragma unroll
            for (int j = 0; j < 4; j++) {
                const int c = tx + 16 * j;
                kv[j] = KP[c * 64 + (k ^ (c & 31))];
            }
            #pragma unroll
            for (int i = 0; i < 4; i++)
                #pragma unroll
                for (int j = 0; j < 4; j++)
                    s[i][j] += qv[i] * kv[j];
        }

        if (kt2 == qt) {
            #pragma unroll
            for (int i = 0; i < 4; i++)
                #pragma unroll
                for (int j = 0; j < 4; j++)
                    if (tx + 16 * j > ty + 16 * i) s[i][j] = -1e30f;
        }

        __syncthreads();

        float p[4][4];
        #pragma unroll
        for (int i = 0; i < 4; i++) {
            float rm = s[i][0];
            #pragma unroll
            for (int j = 1; j < 4; j++) rm = fmaxf(rm, s[i][j]);
            #pragma unroll
            for (int o = 8; o >= 1; o >>= 1)
                rm = fmaxf(rm, __shfl_xor_sync(0xffffffffu, rm, o));
            const float mnew = fmaxf(m_i[i], rm);
            const float corr = __expf(m_i[i] - mnew);
            float rs = 0.0f;
            #pragma unroll
            for (int j = 0; j < 4; j++) {
                p[i][j] = __expf(s[i][j] - mnew);
                rs += p[i][j];
            }
            #pragma unroll
            for (int o = 8; o >= 1; o >>= 1)
                rs += __shfl_xor_sync(0xffffffffu, rs, o);
            l_i[i] = l_i[i] * corr + rs;
            m_i[i] = mnew;
            #pragma unroll
            for (int j = 0; j < 4; j++) acc[i][j] *= corr;
        }

        #pragma unroll
        for (int i = 0; i < 4; i++) {
            const int r = ty + 16 * i;
            const int sw = r & 31;
            #pragma unroll
            for (int j = 0; j < 4; j++) {
                const int c = tx + 16 * j;
                KP[r * 64 + (c ^ sw)] = p[i][j];
            }
        }
        __syncthreads();

        #pragma unroll 8
        for (int k = 0; k < 64; k++) {
            float pv[4], vv[4];
            #pragma unroll
            for (int i = 0; i < 4; i++) {
                const int r = ty + 16 * i;
                pv[i] = KP[r * 64 + (k ^ (r & 31))];
            }
            #pragma unroll
            for (int j = 0; j < 4; j++) vv[j] = Vs[k * 64 + tx + 16 * j];
            #pragma unroll
            for (int i = 0; i < 4; i++)
                #pragma unroll
                for (int j = 0; j < 4; j++)
                    acc[i][j] += pv[i] * vv[j];
        }
    }

    const int b = bh >> 4, h = bh & 15;
    #pragma unroll
    for (int i = 0; i < 4; i++) {
        const int r = ty + 16 * i;
        const float inv = 1.0f / l_i[i];
        const int srow = qbase + r;
        #pragma unroll
        for (int j = 0; j < 4; j++) {
            const int d = tx + 16 * j;
            g_att[(size_t)(b * SEQ + srow) * DMODEL + h * HD + d] = acc[i][j] * inv;
        }
    }
}

// ===========================================================================
extern "C" void kernel_launch(void* const* d_in, const int* in_sizes, int n_in,
                              void* d_out, int out_size)
{
    const float* x     = (const float*)d_in[0];
    // d_in[1] is the causal mask; causality is implemented directly.
    const float* W_qkv = (const float*)d_in[2];
    const float* b_qkv = (const float*)d_in[3];
    const float* W_o   = (const float*)d_in[4];
    const float* b_o   = (const float*)d_in[5];
    float* out = (float*)d_out;

    cudaFuncSetAttribute(tc_gemm_kernel<0>,
                         cudaFuncAttributeMaxDynamicSharedMemorySize, TC_SMEM_BYTES);
    cudaFuncSetAttribute(tc_gemm_kernel<1>,
                         cudaFuncAttributeMaxDynamicSharedMemorySize, TC_SMEM_BYTES);

    float* wqkv_t; cudaGetSymbolAddress((void**)&wqkv_t, g_wqkv_t);
    float* wo_t;   cudaGetSymbolAddress((void**)&wo_t, g_wo_t);
    float* att;    cudaGetSymbolAddress((void**)&att, g_att);

    transpose_kernel<<<dim3(N_QKV / 32, GK / 32), dim3(32, 8)>>>(W_qkv, wqkv_t, GK, N_QKV);
    transpose_kernel<<<dim3(DMODEL / 32, GK / 32), dim3(32, 8)>>>(W_o, wo_t, GK, DMODEL);

    tc_gemm_kernel<0><<<dim3(N_QKV / 128, (BATCH * SEQ) / 128), 256, TC_SMEM_BYTES>>>(
        x, wqkv_t, b_qkv, nullptr);
    attn_kernel<<<dim3(SEQ / 64, BH), 256>>>();
    tc_gemm_kernel<1><<<dim3(DMODEL / 128, (BATCH * SEQ) / 128), 256, TC_SMEM_BYTES>>>(
        att, wo_t, b_o, out);
}

// round 5
// speedup vs baseline: 3.7735x; 2.2334x over previous
#include <cuda_runtime.h>
#include <cstdint>

#define BATCH 2
#define SEQ 2048
#define DMODEL 1024
#define NH 16
#define HD 64
#define BH (BATCH * NH)
#define N_QKV (3 * DMODEL)
#define GK 1024

// Scratch (allocation-free)
__device__ float g_q[BH * SEQ * HD];
__device__ float g_k[BH * SEQ * HD];
__device__ float g_v[BH * SEQ * HD];
__device__ float g_att[BATCH * SEQ * DMODEL];
__device__ float g_wqkv_t[N_QKV * GK];   // [N=3072, K=1024]
__device__ float g_wo_t[DMODEL * GK];    // [N=1024, K=1024]

__device__ __forceinline__ uint32_t f2tf32(float f) {
    uint32_t u;
    asm("cvt.rna.tf32.f32 %0, %1;" : "=r"(u) : "f"(f));
    return u;
}

__device__ __forceinline__ void mma_tf32(
    float& c0, float& c1, float& c2, float& c3,
    uint32_t a0, uint32_t a1, uint32_t a2, uint32_t a3,
    uint32_t b0, uint32_t b1)
{
    asm volatile(
        "mma.sync.aligned.m16n8k8.row.col.f32.tf32.tf32.f32 "
        "{%0,%1,%2,%3}, {%4,%5,%6,%7}, {%8,%9}, {%0,%1,%2,%3};"
        : "+f"(c0), "+f"(c1), "+f"(c2), "+f"(c3)
        : "r"(a0), "r"(a1), "r"(a2), "r"(a3), "r"(b0), "r"(b1));
}

// ===========================================================================
// Transpose: out[c][r] = in[r][c], in is R x C row-major
// ===========================================================================
__global__ void transpose_kernel(const float* __restrict__ in,
                                 float* __restrict__ out, int R, int C)
{
    __shared__ float t[32][33];
    int c0 = blockIdx.x * 32, r0 = blockIdx.y * 32;
    int x = threadIdx.x, y = threadIdx.y;  // block (32, 8)
    #pragma unroll
    for (int i = 0; i < 32; i += 8)
        t[y + i][x] = in[(size_t)(r0 + y + i) * C + c0 + x];
    __syncthreads();
    #pragma unroll
    for (int i = 0; i < 32; i += 8)
        out[(size_t)(c0 + y + i) * R + r0 + x] = t[x][y + i];
}

// ===========================================================================
// tf32 mma.sync GEMM (unchanged from round 4 — passing at ~265us combined)
// ===========================================================================
#define KC 32
#define NKC (GK / KC)
#define ROWSTRIDE 36
#define STAGE_U32 (128 * ROWSTRIDE)
#define TC_SMEM_BYTES (4 * STAGE_U32 * 4)

template<int EPI>
__global__ __launch_bounds__(256, 2) void tc_gemm_kernel(
    const float* __restrict__ A, const float* __restrict__ Bt,
    const float* __restrict__ bias, float* __restrict__ C)
{
    extern __shared__ uint32_t sm[];
    const int tid = threadIdx.x;
    const int wid = tid >> 5, lane = tid & 31;
    const int grp = lane >> 2, tig = lane & 3;
    const int wm = wid >> 1, wn = wid & 1;
    const int m0 = blockIdx.y * 128;
    const int n0 = blockIdx.x * 128;

    const float* Ag = A + (size_t)m0 * GK;
    const float* Bg = Bt + (size_t)n0 * GK;

    const int lr = tid >> 3;
    const int lc = (tid & 7) * 4;

    float acc[2][8][4];
    #pragma unroll
    for (int i = 0; i < 2; i++)
        #pragma unroll
        for (int j = 0; j < 8; j++)
            #pragma unroll
            for (int q = 0; q < 4; q++) acc[i][j][q] = 0.0f;

    {
        #pragma unroll
        for (int i = 0; i < 4; i++) {
            const int r = lr + 32 * i;
            float4 av = *reinterpret_cast<const float4*>(Ag + (size_t)r * GK + lc);
            float4 bv = *reinterpret_cast<const float4*>(Bg + (size_t)r * GK + lc);
            uint32_t* as = sm + r * ROWSTRIDE + lc;
            uint32_t* bs = sm + STAGE_U32 + r * ROWSTRIDE + lc;
            as[0] = f2tf32(av.x); as[1] = f2tf32(av.y);
            as[2] = f2tf32(av.z); as[3] = f2tf32(av.w);
            bs[0] = f2tf32(bv.x); bs[1] = f2tf32(bv.y);
            bs[2] = f2tf32(bv.z); bs[3] = f2tf32(bv.w);
        }
    }
    __syncthreads();

    for (int kc = 0; kc < NKC; kc++) {
        const uint32_t* As = sm + (kc & 1) * 2 * STAGE_U32;
        const uint32_t* Bs = As + STAGE_U32;

        float4 pav[4], pbv[4];
        if (kc + 1 < NKC) {
            const float* An = Ag + (kc + 1) * KC;
            const float* Bn = Bg + (kc + 1) * KC;
            #pragma unroll
            for (int i = 0; i < 4; i++) {
                const int r = lr + 32 * i;
                pav[i] = *reinterpret_cast<const float4*>(An + (size_t)r * GK + lc);
                pbv[i] = *reinterpret_cast<const float4*>(Bn + (size_t)r * GK + lc);
            }
        }

        #pragma unroll
        for (int ks = 0; ks < 4; ks++) {
            const int kof = ks * 8;
            uint32_t af[2][4];
            #pragma unroll
            for (int mt = 0; mt < 2; mt++) {
                const int ab = wm * 32 + mt * 16;
                af[mt][0] = As[(ab + grp) * ROWSTRIDE + kof + tig];
                af[mt][1] = As[(ab + grp + 8) * ROWSTRIDE + kof + tig];
                af[mt][2] = As[(ab + grp) * ROWSTRIDE + kof + tig + 4];
                af[mt][3] = As[(ab + grp + 8) * ROWSTRIDE + kof + tig + 4];
            }
            #pragma unroll
            for (int nt = 0; nt < 8; nt++) {
                const int nb = wn * 64 + nt * 8;
                uint32_t b0 = Bs[(nb + grp) * ROWSTRIDE + kof + tig];
                uint32_t b1 = Bs[(nb + grp) * ROWSTRIDE + kof + tig + 4];
                #pragma unroll
                for (int mt = 0; mt < 2; mt++)
                    mma_tf32(acc[mt][nt][0], acc[mt][nt][1],
                             acc[mt][nt][2], acc[mt][nt][3],
                             af[mt][0], af[mt][1], af[mt][2], af[mt][3],
                             b0, b1);
            }
        }
        __syncthreads();

        if (kc + 1 < NKC) {
            uint32_t* dst = sm + ((kc + 1) & 1) * 2 * STAGE_U32;
            #pragma unroll
            for (int i = 0; i < 4; i++) {
                const int r = lr + 32 * i;
                uint32_t* as = dst + r * ROWSTRIDE + lc;
                uint32_t* bs = dst + STAGE_U32 + r * ROWSTRIDE + lc;
                as[0] = f2tf32(pav[i].x); as[1] = f2tf32(pav[i].y);
                as[2] = f2tf32(pav[i].z); as[3] = f2tf32(pav[i].w);
                bs[0] = f2tf32(pbv[i].x); bs[1] = f2tf32(pbv[i].y);
                bs[2] = f2tf32(pbv[i].z); bs[3] = f2tf32(pbv[i].w);
            }
        }
        __syncthreads();
    }

    #pragma unroll
    for (int mt = 0; mt < 2; mt++) {
        #pragma unroll
        for (int half = 0; half < 2; half++) {
            const int m = m0 + wm * 32 + mt * 16 + grp + half * 8;
            #pragma unroll
            for (int nt = 0; nt < 8; nt++) {
                #pragma unroll
                for (int e = 0; e < 2; e++) {
                    const int n = n0 + wn * 64 + nt * 8 + tig * 2 + e;
                    const float v = acc[mt][nt][half * 2 + e] + __ldg(&bias[n]);
                    if (EPI == 0) {
                        const int b = m >> 11;
                        const int srow = m & (SEQ - 1);
                        const int h = n / 192;
                        const int r = n - h * 192;
                        const int which = r >> 6;
                        const int dd = r & 63;
                        const size_t idx =
                            ((size_t)(b * NH + h) * SEQ + srow) * HD + dd;
                        if (which == 0)      g_q[idx] = v;
                        else if (which == 1) g_k[idx] = v;
                        else                 g_v[idx] = v;
                    } else {
                        C[(size_t)m * DMODEL + n] = v;
                    }
                }
            }
        }
    }
}

// ===========================================================================
// Tensor-core causal flash attention.
// CTA: 128 q-rows x 64-key tiles, 8 warps (warp = m16 x n64).
// Q frags in registers; K/V smem natural layout; P via warp-private smem.
// ===========================================================================
#define AT_STRIDE 68
#define AT_K_OFF (128 * AT_STRIDE)
#define AT_V_OFF (AT_K_OFF + 64 * AT_STRIDE)
#define AT_SMEM_BYTES ((AT_V_OFF + 64 * AT_STRIDE) * 4)

__global__ __launch_bounds__(256) void attn_tc_kernel()
{
    extern __shared__ uint32_t sm[];
    const int tid = threadIdx.x;
    const int wid = tid >> 5, lane = tid & 31;
    const int grp = lane >> 2, tig = lane & 3;
    const int qt = blockIdx.x;           // 0..15 (128-row q tiles)
    const int bh = blockIdx.y;
    const int qbase = qt * 128;
    const int wrow = wid * 16;           // warp row base inside tile

    const float* __restrict__ Qg = g_q + (size_t)bh * SEQ * HD + (size_t)(qbase + wrow) * HD;
    const float* __restrict__ Kg = g_k + (size_t)bh * SEQ * HD;
    const float* __restrict__ Vg = g_v + (size_t)bh * SEQ * HD;

    uint32_t* Ps = sm + wrow * AT_STRIDE;   // warp-private 16 rows
    uint32_t* Ks = sm + AT_K_OFF;
    uint32_t* Vs = sm + AT_V_OFF;

    // ---- stage Q (scaled, tf32) into warp's P region, extract fragments ----
    {
        const int r = lane >> 1, c0 = (lane & 1) * 32;
        #pragma unroll
        for (int i = 0; i < 8; i++) {
            float4 v = *reinterpret_cast<const float4*>(Qg + (size_t)r * HD + c0 + i * 4);
            uint32_t* d = Ps + r * AT_STRIDE + c0 + i * 4;
            d[0] = f2tf32(v.x * 0.125f); d[1] = f2tf32(v.y * 0.125f);
            d[2] = f2tf32(v.z * 0.125f); d[3] = f2tf32(v.w * 0.125f);
        }
    }
    __syncwarp();
    uint32_t aq[8][4];
    #pragma unroll
    for (int ks = 0; ks < 8; ks++) {
        aq[ks][0] = Ps[grp * AT_STRIDE + ks * 8 + tig];
        aq[ks][1] = Ps[(grp + 8) * AT_STRIDE + ks * 8 + tig];
        aq[ks][2] = Ps[grp * AT_STRIDE + ks * 8 + tig + 4];
        aq[ks][3] = Ps[(grp + 8) * AT_STRIDE + ks * 8 + tig + 4];
    }

    float o[8][4];
    #pragma unroll
    for (int nt = 0; nt < 8; nt++)
        #pragma unroll
        for (int q = 0; q < 4; q++) o[nt][q] = 0.0f;
    float m0r = -1e30f, m1r = -1e30f, l0 = 0.0f, l1 = 0.0f;

    const int nkt = 2 * qt + 2;
    for (int kt = 0; kt < nkt; kt++) {
        __syncthreads();   // all warps done reading K/V of previous tile

        // load K,V tile (64x64 each): per thread 4 float4 per operand
        {
            const int r = tid >> 2, c0 = (tid & 3) * 16;
            const float* kp = Kg + (size_t)(kt * 64 + r) * HD + c0;
            const float* vp = Vg + (size_t)(kt * 64 + r) * HD + c0;
            #pragma unroll
            for (int i = 0; i < 4; i++) {
                float4 kv = *reinterpret_cast<const float4*>(kp + i * 4);
                float4 vv = *reinterpret_cast<const float4*>(vp + i * 4);
                uint4 ku = make_uint4(f2tf32(kv.x), f2tf32(kv.y), f2tf32(kv.z), f2tf32(kv.w));
                uint4 vu = make_uint4(f2tf32(vv.x), f2tf32(vv.y), f2tf32(vv.z), f2tf32(vv.w));
                *reinterpret_cast<uint4*>(Ks + r * AT_STRIDE + c0 + i * 4) = ku;
                *reinterpret_cast<uint4*>(Vs + r * AT_STRIDE + c0 + i * 4) = vu;
            }
        }
        __syncthreads();

        // ---- S = Q K^T ----
        float s[8][4];
        #pragma unroll
        for (int nt = 0; nt < 8; nt++)
            #pragma unroll
            for (int q = 0; q < 4; q++) s[nt][q] = 0.0f;

        #pragma unroll
        for (int ks = 0; ks < 8; ks++) {
            #pragma unroll
            for (int nt = 0; nt < 8; nt++) {
                uint32_t b0 = Ks[(nt * 8 + grp) * AT_STRIDE + ks * 8 + tig];
                uint32_t b1 = Ks[(nt * 8 + grp) * AT_STRIDE + ks * 8 + tig + 4];
                mma_tf32(s[nt][0], s[nt][1], s[nt][2], s[nt][3],
                         aq[ks][0], aq[ks][1], aq[ks][2], aq[ks][3], b0, b1);
            }
        }

        // ---- causal mask (last two tiles only) ----
        if (kt >= 2 * qt) {
            const int row0 = qbase + wrow + grp;
            const int colb = kt * 64 + tig * 2;
            #pragma unroll
            for (int nt = 0; nt < 8; nt++) {
                const int c = colb + nt * 8;
                if (c > row0)         s[nt][0] = -1e30f;
                if (c + 1 > row0)     s[nt][1] = -1e30f;
                if (c > row0 + 8)     s[nt][2] = -1e30f;
                if (c + 1 > row0 + 8) s[nt][3] = -1e30f;
            }
        }

        // ---- online softmax (2 rows per thread, quad reduce) ----
        float rm0 = -1e30f, rm1 = -1e30f;
        #pragma unroll
        for (int nt = 0; nt < 8; nt++) {
            rm0 = fmaxf(rm0, fmaxf(s[nt][0], s[nt][1]));
            rm1 = fmaxf(rm1, fmaxf(s[nt][2], s[nt][3]));
        }
        rm0 = fmaxf(rm0, __shfl_xor_sync(0xffffffffu, rm0, 1));
        rm0 = fmaxf(rm0, __shfl_xor_sync(0xffffffffu, rm0, 2));
        rm1 = fmaxf(rm1, __shfl_xor_sync(0xffffffffu, rm1, 1));
        rm1 = fmaxf(rm1, __shfl_xor_sync(0xffffffffu, rm1, 2));

        const float mn0 = fmaxf(m0r, rm0), mn1 = fmaxf(m1r, rm1);
        const float cr0 = __expf(m0r - mn0), cr1 = __expf(m1r - mn1);
        float rs0 = 0.0f, rs1 = 0.0f;
        #pragma unroll
        for (int nt = 0; nt < 8; nt++) {
            s[nt][0] = __expf(s[nt][0] - mn0);
            s[nt][1] = __expf(s[nt][1] - mn0);
            s[nt][2] = __expf(s[nt][2] - mn1);
            s[nt][3] = __expf(s[nt][3] - mn1);
            rs0 += s[nt][0] + s[nt][1];
            rs1 += s[nt][2] + s[nt][3];
        }
        rs0 += __shfl_xor_sync(0xffffffffu, rs0, 1);
        rs0 += __shfl_xor_sync(0xffffffffu, rs0, 2);
        rs1 += __shfl_xor_sync(0xffffffffu, rs1, 1);
        rs1 += __shfl_xor_sync(0xffffffffu, rs1, 2);
        l0 = l0 * cr0 + rs0;  m0r = mn0;
        l1 = l1 * cr1 + rs1;  m1r = mn1;
        #pragma unroll
        for (int nt = 0; nt < 8; nt++) {
            o[nt][0] *= cr0; o[nt][1] *= cr0;
            o[nt][2] *= cr1; o[nt][3] *= cr1;
        }

        // ---- P -> warp-private smem (tf32) ----
        #pragma unroll
        for (int nt = 0; nt < 8; nt++) {
            uint2 v01 = make_uint2(f2tf32(s[nt][0]), f2tf32(s[nt][1]));
            uint2 v23 = make_uint2(f2tf32(s[nt][2]), f2tf32(s[nt][3]));
            *reinterpret_cast<uint2*>(Ps + grp * AT_STRIDE + nt * 8 + tig * 2) = v01;
            *reinterpret_cast<uint2*>(Ps + (grp + 8) * AT_STRIDE + nt * 8 + tig * 2) = v23;
        }
        __syncwarp();

        // ---- O += P V ----
        #pragma unroll
        for (int ks = 0; ks < 8; ks++) {
            uint32_t ap[4];
            ap[0] = Ps[grp * AT_STRIDE + ks * 8 + tig];
            ap[1] = Ps[(grp + 8) * AT_STRIDE + ks * 8 + tig];
            ap[2] = Ps[grp * AT_STRIDE + ks * 8 + tig + 4];
            ap[3] = Ps[(grp + 8) * AT_STRIDE + ks * 8 + tig + 4];
            #pragma unroll
            for (int nt = 0; nt < 8; nt++) {
                uint32_t b0 = Vs[(ks * 8 + tig) * AT_STRIDE + nt * 8 + grp];
                uint32_t b1 = Vs[(ks * 8 + tig + 4) * AT_STRIDE + nt * 8 + grp];
                mma_tf32(o[nt][0], o[nt][1], o[nt][2], o[nt][3],
                         ap[0], ap[1], ap[2], ap[3], b0, b1);
            }
        }
        __syncwarp();   // PV reads of Ps done before next-iter P store
    }

    // ---- write normalized output to g_att [b, s, h*64 + d] ----
    const float inv0 = 1.0f / l0, inv1 = 1.0f / l1;
    const int b = bh >> 4, h = bh & 15;
    const int row0 = qbase + wrow + grp;
    float* o0 = g_att + (size_t)(b * SEQ + row0) * DMODEL + h * HD;
    float* o1 = g_att + (size_t)(b * SEQ + row0 + 8) * DMODEL + h * HD;
    #pragma unroll
    for (int nt = 0; nt < 8; nt++) {
        const int c = nt * 8 + tig * 2;
        *reinterpret_cast<float2*>(o0 + c) = make_float2(o[nt][0] * inv0, o[nt][1] * inv0);
        *reinterpret_cast<float2*>(o1 + c) = make_float2(o[nt][2] * inv1, o[nt][3] * inv1);
    }
}

// ===========================================================================
extern "C" void kernel_launch(void* const* d_in, const int* in_sizes, int n_in,
                              void* d_out, int out_size)
{
    const float* x     = (const float*)d_in[0];
    // d_in[1] is the causal mask; causality is implemented directly.
    const float* W_qkv = (const float*)d_in[2];
    const float* b_qkv = (const float*)d_in[3];
    const float* W_o   = (const float*)d_in[4];
    const float* b_o   = (const float*)d_in[5];
    float* out = (float*)d_out;

    cudaFuncSetAttribute(tc_gemm_kernel<0>,
                         cudaFuncAttributeMaxDynamicSharedMemorySize, TC_SMEM_BYTES);
    cudaFuncSetAttribute(tc_gemm_kernel<1>,
                         cudaFuncAttributeMaxDynamicSharedMemorySize, TC_SMEM_BYTES);
    cudaFuncSetAttribute(attn_tc_kernel,
                         cudaFuncAttributeMaxDynamicSharedMemorySize, AT_SMEM_BYTES);

    float* wqkv_t; cudaGetSymbolAddress((void**)&wqkv_t, g_wqkv_t);
    float* wo_t;   cudaGetSymbolAddress((void**)&wo_t, g_wo_t);
    float* att;    cudaGetSymbolAddress((void**)&att, g_att);

    transpose_kernel<<<dim3(N_QKV / 32, GK / 32), dim3(32, 8)>>>(W_qkv, wqkv_t, GK, N_QKV);
    transpose_kernel<<<dim3(DMODEL / 32, GK / 32), dim3(32, 8)>>>(W_o, wo_t, GK, DMODEL);

    tc_gemm_kernel<0><<<dim3(N_QKV / 128, (BATCH * SEQ) / 128), 256, TC_SMEM_BYTES>>>(
        x, wqkv_t, b_qkv, nullptr);
    attn_tc_kernel<<<dim3(SEQ / 128, BH), 256, AT_SMEM_BYTES>>>();
    tc_gemm_kernel<1><<<dim3(DMODEL / 128, (BATCH * SEQ) / 128), 256, TC_SMEM_BYTES>>>(
        att, wo_t, b_o, out);
}

// round 7
// speedup vs baseline: 4.4716x; 1.1850x over previous
#include <cuda_runtime.h>
#include <cstdint>

#define BATCH 2
#define SEQ 2048
#define DMODEL 1024
#define NH 16
#define HD 64
#define BH (BATCH * NH)
#define N_QKV (3 * DMODEL)
#define GK 1024

// Scratch (allocation-free). g_q/g_k/g_v hold tf32-converted bits (q pre-scaled).
__device__ uint32_t g_q[BH * SEQ * HD];
__device__ uint32_t g_k[BH * SEQ * HD];
__device__ uint32_t g_v[BH * SEQ * HD];
__device__ float g_att[BATCH * SEQ * DMODEL];
__device__ float g_wqkv_t[N_QKV * GK];   // [N=3072, K=1024]
__device__ float g_wo_t[DMODEL * GK];    // [N=1024, K=1024]

__device__ __forceinline__ uint32_t f2tf32(float f) {
    uint32_t u;
    asm("cvt.rna.tf32.f32 %0, %1;" : "=r"(u) : "f"(f));
    return u;
}

__device__ __forceinline__ void mma_tf32(
    float& c0, float& c1, float& c2, float& c3,
    uint32_t a0, uint32_t a1, uint32_t a2, uint32_t a3,
    uint32_t b0, uint32_t b1)
{
    asm volatile(
        "mma.sync.aligned.m16n8k8.row.col.f32.tf32.tf32.f32 "
        "{%0,%1,%2,%3}, {%4,%5,%6,%7}, {%8,%9}, {%0,%1,%2,%3};"
        : "+f"(c0), "+f"(c1), "+f"(c2), "+f"(c3)
        : "r"(a0), "r"(a1), "r"(a2), "r"(a3), "r"(b0), "r"(b1));
}

__device__ __forceinline__ void cp_async16(uint32_t smem_addr, const void* gptr) {
    asm volatile("cp.async.cg.shared.global [%0], [%1], 16;"
                 :: "r"(smem_addr), "l"(gptr) : "memory");
}
#define CP_COMMIT() asm volatile("cp.async.commit_group;" ::: "memory")
#define CP_WAIT(n)  asm volatile("cp.async.wait_group %0;" :: "n"(n) : "memory")

// ===========================================================================
// Transpose: out[c][r] = in[r][c], in is R x C row-major
// ===========================================================================
__global__ void transpose_kernel(const float* __restrict__ in,
                                 float* __restrict__ out, int R, int C)
{
    __shared__ float t[32][33];
    int c0 = blockIdx.x * 32, r0 = blockIdx.y * 32;
    int x = threadIdx.x, y = threadIdx.y;  // block (32, 8)
    #pragma unroll
    for (int i = 0; i < 32; i += 8)
        t[y + i][x] = in[(size_t)(r0 + y + i) * C + c0 + x];
    __syncthreads();
    #pragma unroll
    for (int i = 0; i < 32; i += 8)
        out[(size_t)(c0 + y + i) * R + r0 + x] = t[x][y + i];
}

// ===========================================================================
// tf32 mma.sync GEMM (structure unchanged; EPI 0 emits tf32 bits)
// ===========================================================================
#define KC 32
#define NKC (GK / KC)
#define ROWSTRIDE 36
#define STAGE_U32 (128 * ROWSTRIDE)
#define TC_SMEM_BYTES (4 * STAGE_U32 * 4)

template<int EPI>
__global__ __launch_bounds__(256, 2) void tc_gemm_kernel(
    const float* __restrict__ A, const float* __restrict__ Bt,
    const float* __restrict__ bias, float* __restrict__ C)
{
    extern __shared__ uint32_t sm[];
    const int tid = threadIdx.x;
    const int wid = tid >> 5, lane = tid & 31;
    const int grp = lane >> 2, tig = lane & 3;
    const int wm = wid >> 1, wn = wid & 1;
    const int m0 = blockIdx.y * 128;
    const int n0 = blockIdx.x * 128;

    const float* Ag = A + (size_t)m0 * GK;
    const float* Bg = Bt + (size_t)n0 * GK;

    const int lr = tid >> 3;
    const int lc = (tid & 7) * 4;

    float acc[2][8][4];
    #pragma unroll
    for (int i = 0; i < 2; i++)
        #pragma unroll
        for (int j = 0; j < 8; j++)
            #pragma unroll
            for (int q = 0; q < 4; q++) acc[i][j][q] = 0.0f;

    {
        #pragma unroll
        for (int i = 0; i < 4; i++) {
            const int r = lr + 32 * i;
            float4 av = *reinterpret_cast<const float4*>(Ag + (size_t)r * GK + lc);
            float4 bv = *reinterpret_cast<const float4*>(Bg + (size_t)r * GK + lc);
            uint32_t* as = sm + r * ROWSTRIDE + lc;
            uint32_t* bs = sm + STAGE_U32 + r * ROWSTRIDE + lc;
            as[0] = f2tf32(av.x); as[1] = f2tf32(av.y);
            as[2] = f2tf32(av.z); as[3] = f2tf32(av.w);
            bs[0] = f2tf32(bv.x); bs[1] = f2tf32(bv.y);
            bs[2] = f2tf32(bv.z); bs[3] = f2tf32(bv.w);
        }
    }
    __syncthreads();

    for (int kc = 0; kc < NKC; kc++) {
        const uint32_t* As = sm + (kc & 1) * 2 * STAGE_U32;
        const uint32_t* Bs = As + STAGE_U32;

        float4 pav[4], pbv[4];
        if (kc + 1 < NKC) {
            const float* An = Ag + (kc + 1) * KC;
            const float* Bn = Bg + (kc + 1) * KC;
            #pragma unroll
            for (int i = 0; i < 4; i++) {
                const int r = lr + 32 * i;
                pav[i] = *reinterpret_cast<const float4*>(An + (size_t)r * GK + lc);
                pbv[i] = *reinterpret_cast<const float4*>(Bn + (size_t)r * GK + lc);
            }
        }

        #pragma unroll
        for (int ks = 0; ks < 4; ks++) {
            const int kof = ks * 8;
            uint32_t af[2][4];
            #pragma unroll
            for (int mt = 0; mt < 2; mt++) {
                const int ab = wm * 32 + mt * 16;
                af[mt][0] = As[(ab + grp) * ROWSTRIDE + kof + tig];
                af[mt][1] = As[(ab + grp + 8) * ROWSTRIDE + kof + tig];
                af[mt][2] = As[(ab + grp) * ROWSTRIDE + kof + tig + 4];
                af[mt][3] = As[(ab + grp + 8) * ROWSTRIDE + kof + tig + 4];
            }
            #pragma unroll
            for (int nt = 0; nt < 8; nt++) {
                const int nb = wn * 64 + nt * 8;
                uint32_t b0 = Bs[(nb + grp) * ROWSTRIDE + kof + tig];
                uint32_t b1 = Bs[(nb + grp) * ROWSTRIDE + kof + tig + 4];
                #pragma unroll
                for (int mt = 0; mt < 2; mt++)
                    mma_tf32(acc[mt][nt][0], acc[mt][nt][1],
                             acc[mt][nt][2], acc[mt][nt][3],
                             af[mt][0], af[mt][1], af[mt][2], af[mt][3],
                             b0, b1);
            }
        }
        __syncthreads();

        if (kc + 1 < NKC) {
            uint32_t* dst = sm + ((kc + 1) & 1) * 2 * STAGE_U32;
            #pragma unroll
            for (int i = 0; i < 4; i++) {
                const int r = lr + 32 * i;
                uint32_t* as = dst + r * ROWSTRIDE + lc;
                uint32_t* bs = dst + STAGE_U32 + r * ROWSTRIDE + lc;
                as[0] = f2tf32(pav[i].x); as[1] = f2tf32(pav[i].y);
                as[2] = f2tf32(pav[i].z); as[3] = f2tf32(pav[i].w);
                bs[0] = f2tf32(pbv[i].x); bs[1] = f2tf32(pbv[i].y);
                bs[2] = f2tf32(pbv[i].z); bs[3] = f2tf32(pbv[i].w);
            }
        }
        __syncthreads();
    }

    #pragma unroll
    for (int mt = 0; mt < 2; mt++) {
        #pragma unroll
        for (int half = 0; half < 2; half++) {
            const int m = m0 + wm * 32 + mt * 16 + grp + half * 8;
            #pragma unroll
            for (int nt = 0; nt < 8; nt++) {
                #pragma unroll
                for (int e = 0; e < 2; e++) {
                    const int n = n0 + wn * 64 + nt * 8 + tig * 2 + e;
                    const float v = acc[mt][nt][half * 2 + e] + __ldg(&bias[n]);
                    if (EPI == 0) {
                        const int b = m >> 11;
                        const int srow = m & (SEQ - 1);
                        const int h = n / 192;
                        const int r = n - h * 192;
                        const int which = r >> 6;
                        const int dd = r & 63;
                        const size_t idx =
                            ((size_t)(b * NH + h) * SEQ + srow) * HD + dd;
                        if (which == 0)      g_q[idx] = f2tf32(v * 0.125f);
                        else if (which == 1) g_k[idx] = f2tf32(v);
                        else                 g_v[idx] = f2tf32(v);
                    } else {
                        C[(size_t)m * DMODEL + n] = v;
                    }
                }
            }
        }
    }
}

// ===========================================================================
// Tensor-core causal flash attention, cp.async double-buffered K/V.
// CTA: 128 q-rows x 64-key tiles, 8 warps (warp = m16 x n64).
// Grid: 1-D 512, LPT order (heavy qt first).
// ===========================================================================
#define AT_STRIDE 68
#define AT_P_WORDS (128 * AT_STRIDE)      // P staging region (per-warp 16 rows)
#define AT_STAGE_WORDS (64 * AT_STRIDE)   // one operand tile
// layout: P | K0 | V0 | K1 | V1
#define AT_SMEM_BYTES ((AT_P_WORDS + 4 * AT_STAGE_WORDS) * 4)

__global__ __launch_bounds__(256) void attn_tc_kernel()
{
    extern __shared__ uint32_t sm[];
    uint32_t smb;
    asm("{ .reg .u64 t; cvta.to.shared.u64 t, %1; cvt.u32.u64 %0, t; }"
        : "=r"(smb) : "l"(sm));

    const int tid = threadIdx.x;
    const int wid = tid >> 5, lane = tid & 31;
    const int grp = lane >> 2, tig = lane & 3;
    const int bid = blockIdx.x;
    const int qt = (SEQ / 128 - 1) - (bid >> 5);   // heavy tiles first
    const int bh = bid & 31;
    const int qbase = qt * 128;
    const int wrow = wid * 16;

    const uint32_t* __restrict__ Qu = g_q + (size_t)bh * SEQ * HD + (size_t)(qbase + wrow) * HD;
    const uint32_t* __restrict__ Ku = g_k + (size_t)bh * SEQ * HD;
    const uint32_t* __restrict__ Vu = g_v + (size_t)bh * SEQ * HD;

    uint32_t* Ps = sm + wrow * AT_STRIDE;

    // ---- Q fragments straight from global (tf32 bits, pre-scaled) ----
    uint32_t aq[8][4];
    #pragma unroll
    for (int ks = 0; ks < 8; ks++) {
        aq[ks][0] = __ldg(&Qu[grp * HD + ks * 8 + tig]);
        aq[ks][1] = __ldg(&Qu[(grp + 8) * HD + ks * 8 + tig]);
        aq[ks][2] = __ldg(&Qu[grp * HD + ks * 8 + tig + 4]);
        aq[ks][3] = __ldg(&Qu[(grp + 8) * HD + ks * 8 + tig + 4]);
    }

    float o[8][4];
    #pragma unroll
    for (int nt = 0; nt < 8; nt++)
        #pragma unroll
        for (int q = 0; q < 4; q++) o[nt][q] = 0.0f;
    float m0r = -1e30f, m1r = -1e30f, l0 = 0.0f, l1 = 0.0f;

    const int nkt = 2 * qt + 2;

    // per-thread cp.async chunk coords (4 chunks of 16B per operand per tile)
    const int cr = tid >> 2;            // row 0..63
    const int cc = (tid & 3) * 16;      // word col 0,16,32,48

    // prologue: tile 0 -> stage 0
    {
        const uint32_t ksm = smb + (AT_P_WORDS) * 4;
        const uint32_t vsm = ksm + AT_STAGE_WORDS * 4;
        #pragma unroll
        for (int i = 0; i < 4; i++) {
            cp_async16(ksm + (cr * AT_STRIDE + cc + i * 4) * 4, Ku + (size_t)cr * HD + cc + i * 4);
            cp_async16(vsm + (cr * AT_STRIDE + cc + i * 4) * 4, Vu + (size_t)cr * HD + cc + i * 4);
        }
        CP_COMMIT();
    }

    for (int kt = 0; kt < nkt; kt++) {
        if (kt + 1 < nkt) {
            const int st = (kt + 1) & 1;
            const uint32_t ksm = smb + (AT_P_WORDS + st * 2 * AT_STAGE_WORDS) * 4;
            const uint32_t vsm = ksm + AT_STAGE_WORDS * 4;
            const uint32_t* kg = Ku + (size_t)(kt + 1) * 64 * HD;
            const uint32_t* vg = Vu + (size_t)(kt + 1) * 64 * HD;
            #pragma unroll
            for (int i = 0; i < 4; i++) {
                cp_async16(ksm + (cr * AT_STRIDE + cc + i * 4) * 4, kg + (size_t)cr * HD + cc + i * 4);
                cp_async16(vsm + (cr * AT_STRIDE + cc + i * 4) * 4, vg + (size_t)cr * HD + cc + i * 4);
            }
            CP_COMMIT();
            CP_WAIT(1);
        } else {
            CP_WAIT(0);
        }
        __syncthreads();   // tile kt resident for all warps

        const uint32_t* Ks = sm + AT_P_WORDS + (kt & 1) * 2 * AT_STAGE_WORDS;
        const uint32_t* Vs = Ks + AT_STAGE_WORDS;

        // ---- S = Q K^T ----
        float s[8][4];
        #pragma unroll
        for (int nt = 0; nt < 8; nt++)
            #pragma unroll
            for (int q = 0; q < 4; q++) s[nt][q] = 0.0f;

        #pragma unroll
        for (int ks = 0; ks < 8; ks++) {
            #pragma unroll
            for (int nt = 0; nt < 8; nt++) {
                uint32_t b0 = Ks[(nt * 8 + grp) * AT_STRIDE + ks * 8 + tig];
                uint32_t b1 = Ks[(nt * 8 + grp) * AT_STRIDE + ks * 8 + tig + 4];
                mma_tf32(s[nt][0], s[nt][1], s[nt][2], s[nt][3],
                         aq[ks][0], aq[ks][1], aq[ks][2], aq[ks][3], b0, b1);
            }
        }

        // ---- causal mask (last two tiles only) ----
        if (kt >= 2 * qt) {
            const int row0 = qbase + wrow + grp;
            const int colb = kt * 64 + tig * 2;
            #pragma unroll
            for (int nt = 0; nt < 8; nt++) {
                const int c = colb + nt * 8;
                if (c > row0)         s[nt][0] = -1e30f;
                if (c + 1 > row0)     s[nt][1] = -1e30f;
                if (c > row0 + 8)     s[nt][2] = -1e30f;
                if (c + 1 > row0 + 8) s[nt][3] = -1e30f;
            }
        }

        // ---- online softmax (2 rows per thread, quad reduce) ----
        float rm0 = -1e30f, rm1 = -1e30f;
        #pragma unroll
        for (int nt = 0; nt < 8; nt++) {
            rm0 = fmaxf(rm0, fmaxf(s[nt][0], s[nt][1]));
            rm1 = fmaxf(rm1, fmaxf(s[nt][2], s[nt][3]));
        }
        rm0 = fmaxf(rm0, __shfl_xor_sync(0xffffffffu, rm0, 1));
        rm0 = fmaxf(rm0, __shfl_xor_sync(0xffffffffu, rm0, 2));
        rm1 = fmaxf(rm1, __shfl_xor_sync(0xffffffffu, rm1, 1));
        rm1 = fmaxf(rm1, __shfl_xor_sync(0xffffffffu, rm1, 2));

        const float mn0 = fmaxf(m0r, rm0), mn1 = fmaxf(m1r, rm1);
        const float cr0 = __expf(m0r - mn0), cr1 = __expf(m1r - mn1);
        float rs0 = 0.0f, rs1 = 0.0f;
        #pragma unroll
        for (int nt = 0; nt < 8; nt++) {
            s[nt][0] = __expf(s[nt][0] - mn0);
            s[nt][1] = __expf(s[nt][1] - mn0);
            s[nt][2] = __expf(s[nt][2] - mn1);
            s[nt][3] = __expf(s[nt][3] - mn1);
            rs0 += s[nt][0] + s[nt][1];
            rs1 += s[nt][2] + s[nt][3];
        }
        rs0 += __shfl_xor_sync(0xffffffffu, rs0, 1);
        rs0 += __shfl_xor_sync(0xffffffffu, rs0, 2);
        rs1 += __shfl_xor_sync(0xffffffffu, rs1, 1);
        rs1 += __shfl_xor_sync(0xffffffffu, rs1, 2);
        l0 = l0 * cr0 + rs0;  m0r = mn0;
        l1 = l1 * cr1 + rs1;  m1r = mn1;
        #pragma unroll
        for (int nt = 0; nt < 8; nt++) {
            o[nt][0] *= cr0; o[nt][1] *= cr0;
            o[nt][2] *= cr1; o[nt][3] *= cr1;
        }

        // ---- P -> warp-private smem (tf32) ----
        #pragma unroll
        for (int nt = 0; nt < 8; nt++) {
            uint2 v01 = make_uint2(f2tf32(s[nt][0]), f2tf32(s[nt][1]));
            uint2 v23 = make_uint2(f2tf32(s[nt][2]), f2tf32(s[nt][3]));
            *reinterpret_cast<uint2*>(Ps + grp * AT_STRIDE + nt * 8 + tig * 2) = v01;
            *reinterpret_cast<uint2*>(Ps + (grp + 8) * AT_STRIDE + nt * 8 + tig * 2) = v23;
        }
        __syncwarp();

        // ---- O += P V ----
        #pragma unroll
        for (int ks = 0; ks < 8; ks++) {
            uint32_t ap[4];
            ap[0] = Ps[grp * AT_STRIDE + ks * 8 + tig];
            ap[1] = Ps[(grp + 8) * AT_STRIDE + ks * 8 + tig];
            ap[2] = Ps[grp * AT_STRIDE + ks * 8 + tig + 4];
            ap[3] = Ps[(grp + 8) * AT_STRIDE + ks * 8 + tig + 4];
            #pragma unroll
            for (int nt = 0; nt < 8; nt++) {
                uint32_t b0 = Vs[(ks * 8 + tig) * AT_STRIDE + nt * 8 + grp];
                uint32_t b1 = Vs[(ks * 8 + tig + 4) * AT_STRIDE + nt * 8 + grp];
                mma_tf32(o[nt][0], o[nt][1], o[nt][2], o[nt][3],
                         ap[0], ap[1], ap[2], ap[3], b0, b1);
            }
        }
        __syncthreads();   // all warps done with stage kt before its reuse
    }

    // ---- write normalized output to g_att [b, s, h*64 + d] ----
    const float inv0 = 1.0f / l0, inv1 = 1.0f / l1;
    const int b = bh >> 4, h = bh & 15;
    const int row0 = qbase + wrow + grp;
    float* o0 = g_att + (size_t)(b * SEQ + row0) * DMODEL + h * HD;
    float* o1 = g_att + (size_t)(b * SEQ + row0 + 8) * DMODEL + h * HD;
    #pragma unroll
    for (int nt = 0; nt < 8; nt++) {
        const int c = nt * 8 + tig * 2;
        *reinterpret_cast<float2*>(o0 + c) = make_float2(o[nt][0] * inv0, o[nt][1] * inv0);
        *reinterpret_cast<float2*>(o1 + c) = make_float2(o[nt][2] * inv1, o[nt][3] * inv1);
    }
}

// ===========================================================================
extern "C" void kernel_launch(void* const* d_in, const int* in_sizes, int n_in,
                              void* d_out, int out_size)
{
    const float* x     = (const float*)d_in[0];
    // d_in[1] is the causal mask; causality is implemented directly.
    const float* W_qkv = (const float*)d_in[2];
    const float* b_qkv = (const float*)d_in[3];
    const float* W_o   = (const float*)d_in[4];
    const float* b_o   = (const float*)d_in[5];
    float* out = (float*)d_out;

    cudaFuncSetAttribute(tc_gemm_kernel<0>,
                         cudaFuncAttributeMaxDynamicSharedMemorySize, TC_SMEM_BYTES);
    cudaFuncSetAttribute(tc_gemm_kernel<1>,
                         cudaFuncAttributeMaxDynamicSharedMemorySize, TC_SMEM_BYTES);
    cudaFuncSetAttribute(attn_tc_kernel,
                         cudaFuncAttributeMaxDynamicSharedMemorySize, AT_SMEM_BYTES);

    float* wqkv_t; cudaGetSymbolAddress((void**)&wqkv_t, g_wqkv_t);
    float* wo_t;   cudaGetSymbolAddress((void**)&wo_t, g_wo_t);
    float* att;    cudaGetSymbolAddress((void**)&att, g_att);

    transpose_kernel<<<dim3(N_QKV / 32, GK / 32), dim3(32, 8)>>>(W_qkv, wqkv_t, GK, N_QKV);
    transpose_kernel<<<dim3(DMODEL / 32, GK / 32), dim3(32, 8)>>>(W_o, wo_t, GK, DMODEL);

    tc_gemm_kernel<0><<<dim3(N_QKV / 128, (BATCH * SEQ) / 128), 256, TC_SMEM_BYTES>>>(
        x, wqkv_t, b_qkv, nullptr);
    attn_tc_kernel<<<(SEQ / 128) * BH, 256, AT_SMEM_BYTES>>>();
    tc_gemm_kernel<1><<<dim3(DMODEL / 128, (BATCH * SEQ) / 128), 256, TC_SMEM_BYTES>>>(
        att, wo_t, b_o, out);
}

// round 8
// speedup vs baseline: 4.6147x; 1.0320x over previous
#include <cuda_runtime.h>
#include <cstdint>

#define BATCH 2
#define SEQ 2048
#define DMODEL 1024
#define NH 16
#define HD 64
#define BH (BATCH * NH)
#define N_QKV (3 * DMODEL)
#define GK 1024

// Scratch (allocation-free). g_q/g_k/g_v hold tf32-converted bits (q pre-scaled).
__device__ uint32_t g_q[BH * SEQ * HD];
__device__ uint32_t g_k[BH * SEQ * HD];
__device__ uint32_t g_v[BH * SEQ * HD];
__device__ float g_att[BATCH * SEQ * DMODEL];
__device__ float g_wqkv_t[N_QKV * GK];   // [N=3072, K=1024]
__device__ float g_wo_t[DMODEL * GK];    // [N=1024, K=1024]

__device__ __forceinline__ uint32_t f2tf32(float f) {
    uint32_t u;
    asm("cvt.rna.tf32.f32 %0, %1;" : "=r"(u) : "f"(f));
    return u;
}

__device__ __forceinline__ void mma_tf32(
    float& c0, float& c1, float& c2, float& c3,
    uint32_t a0, uint32_t a1, uint32_t a2, uint32_t a3,
    uint32_t b0, uint32_t b1)
{
    asm volatile(
        "mma.sync.aligned.m16n8k8.row.col.f32.tf32.tf32.f32 "
        "{%0,%1,%2,%3}, {%4,%5,%6,%7}, {%8,%9}, {%0,%1,%2,%3};"
        : "+f"(c0), "+f"(c1), "+f"(c2), "+f"(c3)
        : "r"(a0), "r"(a1), "r"(a2), "r"(a3), "r"(b0), "r"(b1));
}

__device__ __forceinline__ void cp_async16(uint32_t smem_addr, const void* gptr) {
    asm volatile("cp.async.cg.shared.global [%0], [%1], 16;"
                 :: "r"(smem_addr), "l"(gptr) : "memory");
}
#define CP_COMMIT() asm volatile("cp.async.commit_group;" ::: "memory")
#define CP_WAIT(n)  asm volatile("cp.async.wait_group %0;" :: "n"(n) : "memory")

// ===========================================================================
// Transpose: out[c][r] = in[r][c], in is R x C row-major
// ===========================================================================
__global__ void transpose_kernel(const float* __restrict__ in,
                                 float* __restrict__ out, int R, int C)
{
    __shared__ float t[32][33];
    int c0 = blockIdx.x * 32, r0 = blockIdx.y * 32;
    int x = threadIdx.x, y = threadIdx.y;  // block (32, 8)
    #pragma unroll
    for (int i = 0; i < 32; i += 8)
        t[y + i][x] = in[(size_t)(r0 + y + i) * C + c0 + x];
    __syncthreads();
    #pragma unroll
    for (int i = 0; i < 32; i += 8)
        out[(size_t)(c0 + y + i) * R + r0 + x] = t[x][y + i];
}

// ===========================================================================
// tf32 mma.sync GEMM (unchanged; EPI 0 emits tf32 bits)
// ===========================================================================
#define KC 32
#define NKC (GK / KC)
#define ROWSTRIDE 36
#define STAGE_U32 (128 * ROWSTRIDE)
#define TC_SMEM_BYTES (4 * STAGE_U32 * 4)

template<int EPI>
__global__ __launch_bounds__(256, 2) void tc_gemm_kernel(
    const float* __restrict__ A, const float* __restrict__ Bt,
    const float* __restrict__ bias, float* __restrict__ C)
{
    extern __shared__ uint32_t sm[];
    const int tid = threadIdx.x;
    const int wid = tid >> 5, lane = tid & 31;
    const int grp = lane >> 2, tig = lane & 3;
    const int wm = wid >> 1, wn = wid & 1;
    const int m0 = blockIdx.y * 128;
    const int n0 = blockIdx.x * 128;

    const float* Ag = A + (size_t)m0 * GK;
    const float* Bg = Bt + (size_t)n0 * GK;

    const int lr = tid >> 3;
    const int lc = (tid & 7) * 4;

    float acc[2][8][4];
    #pragma unroll
    for (int i = 0; i < 2; i++)
        #pragma unroll
        for (int j = 0; j < 8; j++)
            #pragma unroll
            for (int q = 0; q < 4; q++) acc[i][j][q] = 0.0f;

    {
        #pragma unroll
        for (int i = 0; i < 4; i++) {
            const int r = lr + 32 * i;
            float4 av = *reinterpret_cast<const float4*>(Ag + (size_t)r * GK + lc);
            float4 bv = *reinterpret_cast<const float4*>(Bg + (size_t)r * GK + lc);
            uint32_t* as = sm + r * ROWSTRIDE + lc;
            uint32_t* bs = sm + STAGE_U32 + r * ROWSTRIDE + lc;
            as[0] = f2tf32(av.x); as[1] = f2tf32(av.y);
            as[2] = f2tf32(av.z); as[3] = f2tf32(av.w);
            bs[0] = f2tf32(bv.x); bs[1] = f2tf32(bv.y);
            bs[2] = f2tf32(bv.z); bs[3] = f2tf32(bv.w);
        }
    }
    __syncthreads();

    for (int kc = 0; kc < NKC; kc++) {
        const uint32_t* As = sm + (kc & 1) * 2 * STAGE_U32;
        const uint32_t* Bs = As + STAGE_U32;

        float4 pav[4], pbv[4];
        if (kc + 1 < NKC) {
            const float* An = Ag + (kc + 1) * KC;
            const float* Bn = Bg + (kc + 1) * KC;
            #pragma unroll
            for (int i = 0; i < 4; i++) {
                const int r = lr + 32 * i;
                pav[i] = *reinterpret_cast<const float4*>(An + (size_t)r * GK + lc);
                pbv[i] = *reinterpret_cast<const float4*>(Bn + (size_t)r * GK + lc);
            }
        }

        #pragma unroll
        for (int ks = 0; ks < 4; ks++) {
            const int kof = ks * 8;
            uint32_t af[2][4];
            #pragma unroll
            for (int mt = 0; mt < 2; mt++) {
                const int ab = wm * 32 + mt * 16;
                af[mt][0] = As[(ab + grp) * ROWSTRIDE + kof + tig];
                af[mt][1] = As[(ab + grp + 8) * ROWSTRIDE + kof + tig];
                af[mt][2] = As[(ab + grp) * ROWSTRIDE + kof + tig + 4];
                af[mt][3] = As[(ab + grp + 8) * ROWSTRIDE + kof + tig + 4];
            }
            #pragma unroll
            for (int nt = 0; nt < 8; nt++) {
                const int nb = wn * 64 + nt * 8;
                uint32_t b0 = Bs[(nb + grp) * ROWSTRIDE + kof + tig];
                uint32_t b1 = Bs[(nb + grp) * ROWSTRIDE + kof + tig + 4];
                #pragma unroll
                for (int mt = 0; mt < 2; mt++)
                    mma_tf32(acc[mt][nt][0], acc[mt][nt][1],
                             acc[mt][nt][2], acc[mt][nt][3],
                             af[mt][0], af[mt][1], af[mt][2], af[mt][3],
                             b0, b1);
            }
        }
        __syncthreads();

        if (kc + 1 < NKC) {
            uint32_t* dst = sm + ((kc + 1) & 1) * 2 * STAGE_U32;
            #pragma unroll
            for (int i = 0; i < 4; i++) {
                const int r = lr + 32 * i;
                uint32_t* as = dst + r * ROWSTRIDE + lc;
                uint32_t* bs = dst + STAGE_U32 + r * ROWSTRIDE + lc;
                as[0] = f2tf32(pav[i].x); as[1] = f2tf32(pav[i].y);
                as[2] = f2tf32(pav[i].z); as[3] = f2tf32(pav[i].w);
                bs[0] = f2tf32(pbv[i].x); bs[1] = f2tf32(pbv[i].y);
                bs[2] = f2tf32(pbv[i].z); bs[3] = f2tf32(pbv[i].w);
            }
        }
        __syncthreads();
    }

    #pragma unroll
    for (int mt = 0; mt < 2; mt++) {
        #pragma unroll
        for (int half = 0; half < 2; half++) {
            const int m = m0 + wm * 32 + mt * 16 + grp + half * 8;
            #pragma unroll
            for (int nt = 0; nt < 8; nt++) {
                #pragma unroll
                for (int e = 0; e < 2; e++) {
                    const int n = n0 + wn * 64 + nt * 8 + tig * 2 + e;
                    const float v = acc[mt][nt][half * 2 + e] + __ldg(&bias[n]);
                    if (EPI == 0) {
                        const int b = m >> 11;
                        const int srow = m & (SEQ - 1);
                        const int h = n / 192;
                        const int r = n - h * 192;
                        const int which = r >> 6;
                        const int dd = r & 63;
                        const size_t idx =
                            ((size_t)(b * NH + h) * SEQ + srow) * HD + dd;
                        if (which == 0)      g_q[idx] = f2tf32(v * 0.125f);
                        else if (which == 1) g_k[idx] = f2tf32(v);
                        else                 g_v[idx] = f2tf32(v);
                    } else {
                        C[(size_t)m * DMODEL + n] = v;
                    }
                }
            }
        }
    }
}

// ===========================================================================
// Tensor-core causal flash attention, cp.async double-buffered K/V.
// P kept in registers; C-frag -> A-frag via intra-quad shuffles (no P smem).
// smem = 4 * 64x68 words = 68KB -> 2 CTAs/SM.
// Grid: 1-D 512, LPT order (heavy qt first).
// ===========================================================================
#define AT_STRIDE 68
#define AT_STAGE_WORDS (64 * AT_STRIDE)   // one operand tile
// layout: K0 | V0 | K1 | V1
#define AT_SMEM_BYTES (4 * AT_STAGE_WORDS * 4)

__global__ __launch_bounds__(256, 2) void attn_tc_kernel()
{
    extern __shared__ uint32_t sm[];
    uint32_t smb;
    asm("{ .reg .u64 t; cvta.to.shared.u64 t, %1; cvt.u32.u64 %0, t; }"
        : "=r"(smb) : "l"(sm));

    const int tid = threadIdx.x;
    const int wid = tid >> 5, lane = tid & 31;
    const int grp = lane >> 2, tig = lane & 3;
    const int bid = blockIdx.x;
    const int qt = (SEQ / 128 - 1) - (bid >> 5);   // heavy tiles first
    const int bh = bid & 31;
    const int qbase = qt * 128;
    const int wrow = wid * 16;

    const uint32_t* __restrict__ Qu = g_q + (size_t)bh * SEQ * HD + (size_t)(qbase + wrow) * HD;
    const uint32_t* __restrict__ Ku = g_k + (size_t)bh * SEQ * HD;
    const uint32_t* __restrict__ Vu = g_v + (size_t)bh * SEQ * HD;

    // ---- Q fragments straight from global (tf32 bits, pre-scaled) ----
    uint32_t aq[8][4];
    #pragma unroll
    for (int ks = 0; ks < 8; ks++) {
        aq[ks][0] = __ldg(&Qu[grp * HD + ks * 8 + tig]);
        aq[ks][1] = __ldg(&Qu[(grp + 8) * HD + ks * 8 + tig]);
        aq[ks][2] = __ldg(&Qu[grp * HD + ks * 8 + tig + 4]);
        aq[ks][3] = __ldg(&Qu[(grp + 8) * HD + ks * 8 + tig + 4]);
    }

    float o[8][4];
    #pragma unroll
    for (int nt = 0; nt < 8; nt++)
        #pragma unroll
        for (int q = 0; q < 4; q++) o[nt][q] = 0.0f;
    float m0r = -1e30f, m1r = -1e30f, l0 = 0.0f, l1 = 0.0f;

    const int nkt = 2 * qt + 2;

    // per-thread cp.async chunk coords (4 chunks of 16B per operand per tile)
    const int cr = tid >> 2;            // row 0..63
    const int cc = (tid & 3) * 16;      // word col 0,16,32,48

    // prologue: tile 0 -> stage 0
    {
        const uint32_t ksm = smb;
        const uint32_t vsm = ksm + AT_STAGE_WORDS * 4;
        #pragma unroll
        for (int i = 0; i < 4; i++) {
            cp_async16(ksm + (cr * AT_STRIDE + cc + i * 4) * 4, Ku + (size_t)cr * HD + cc + i * 4);
            cp_async16(vsm + (cr * AT_STRIDE + cc + i * 4) * 4, Vu + (size_t)cr * HD + cc + i * 4);
        }
        CP_COMMIT();
    }

    const int src_lo = (grp << 2) | (tig >> 1);
    const int src_hi = src_lo + 2;
    const bool odd = (tig & 1) != 0;

    for (int kt = 0; kt < nkt; kt++) {
        if (kt + 1 < nkt) {
            const int st = (kt + 1) & 1;
            const uint32_t ksm = smb + (st * 2 * AT_STAGE_WORDS) * 4;
            const uint32_t vsm = ksm + AT_STAGE_WORDS * 4;
            const uint32_t* kg = Ku + (size_t)(kt + 1) * 64 * HD;
            const uint32_t* vg = Vu + (size_t)(kt + 1) * 64 * HD;
            #pragma unroll
            for (int i = 0; i < 4; i++) {
                cp_async16(ksm + (cr * AT_STRIDE + cc + i * 4) * 4, kg + (size_t)cr * HD + cc + i * 4);
                cp_async16(vsm + (cr * AT_STRIDE + cc + i * 4) * 4, vg + (size_t)cr * HD + cc + i * 4);
            }
            CP_COMMIT();
            CP_WAIT(1);
        } else {
            CP_WAIT(0);
        }
        __syncthreads();   // tile kt resident for all warps

        const uint32_t* Ks = sm + (kt & 1) * 2 * AT_STAGE_WORDS;
        const uint32_t* Vs = Ks + AT_STAGE_WORDS;

        // ---- S = Q K^T ----
        float s[8][4];
        #pragma unroll
        for (int nt = 0; nt < 8; nt++)
            #pragma unroll
            for (int q = 0; q < 4; q++) s[nt][q] = 0.0f;

        #pragma unroll
        for (int ks = 0; ks < 8; ks++) {
            #pragma unroll
            for (int nt = 0; nt < 8; nt++) {
                uint32_t b0 = Ks[(nt * 8 + grp) * AT_STRIDE + ks * 8 + tig];
                uint32_t b1 = Ks[(nt * 8 + grp) * AT_STRIDE + ks * 8 + tig + 4];
                mma_tf32(s[nt][0], s[nt][1], s[nt][2], s[nt][3],
                         aq[ks][0], aq[ks][1], aq[ks][2], aq[ks][3], b0, b1);
            }
        }

        // ---- causal mask (last two tiles only) ----
        if (kt >= 2 * qt) {
            const int row0 = qbase + wrow + grp;
            const int colb = kt * 64 + tig * 2;
            #pragma unroll
            for (int nt = 0; nt < 8; nt++) {
                const int c = colb + nt * 8;
                if (c > row0)         s[nt][0] = -1e30f;
                if (c + 1 > row0)     s[nt][1] = -1e30f;
                if (c > row0 + 8)     s[nt][2] = -1e30f;
                if (c + 1 > row0 + 8) s[nt][3] = -1e30f;
            }
        }

        // ---- online softmax (2 rows per thread, quad reduce) ----
        float rm0 = -1e30f, rm1 = -1e30f;
        #pragma unroll
        for (int nt = 0; nt < 8; nt++) {
            rm0 = fmaxf(rm0, fmaxf(s[nt][0], s[nt][1]));
            rm1 = fmaxf(rm1, fmaxf(s[nt][2], s[nt][3]));
        }
        rm0 = fmaxf(rm0, __shfl_xor_sync(0xffffffffu, rm0, 1));
        rm0 = fmaxf(rm0, __shfl_xor_sync(0xffffffffu, rm0, 2));
        rm1 = fmaxf(rm1, __shfl_xor_sync(0xffffffffu, rm1, 1));
        rm1 = fmaxf(rm1, __shfl_xor_sync(0xffffffffu, rm1, 2));

        const float mn0 = fmaxf(m0r, rm0), mn1 = fmaxf(m1r, rm1);
        const float cr0 = __expf(m0r - mn0), cr1 = __expf(m1r - mn1);
        float rs0 = 0.0f, rs1 = 0.0f;
        #pragma unroll
        for (int nt = 0; nt < 8; nt++) {
            s[nt][0] = __expf(s[nt][0] - mn0);
            s[nt][1] = __expf(s[nt][1] - mn0);
            s[nt][2] = __expf(s[nt][2] - mn1);
            s[nt][3] = __expf(s[nt][3] - mn1);
            rs0 += s[nt][0] + s[nt][1];
            rs1 += s[nt][2] + s[nt][3];
        }
        rs0 += __shfl_xor_sync(0xffffffffu, rs0, 1);
        rs0 += __shfl_xor_sync(0xffffffffu, rs0, 2);
        rs1 += __shfl_xor_sync(0xffffffffu, rs1, 1);
        rs1 += __shfl_xor_sync(0xffffffffu, rs1, 2);
        l0 = l0 * cr0 + rs0;  m0r = mn0;
        l1 = l1 * cr1 + rs1;  m1r = mn1;
        #pragma unroll
        for (int nt = 0; nt < 8; nt++) {
            o[nt][0] *= cr0; o[nt][1] *= cr0;
            o[nt][2] *= cr1; o[nt][3] *= cr1;
        }

        // ---- O += P V : P stays in registers; C-frag -> A-frag by shuffle ----
        #pragma unroll
        for (int ks = 0; ks < 8; ks++) {
            const uint32_t p0 = f2tf32(s[ks][0]);
            const uint32_t p1 = f2tf32(s[ks][1]);
            const uint32_t p2 = f2tf32(s[ks][2]);
            const uint32_t p3 = f2tf32(s[ks][3]);
            const uint32_t e0lo = __shfl_sync(0xffffffffu, p0, src_lo);
            const uint32_t e1lo = __shfl_sync(0xffffffffu, p1, src_lo);
            const uint32_t f0lo = __shfl_sync(0xffffffffu, p2, src_lo);
            const uint32_t f1lo = __shfl_sync(0xffffffffu, p3, src_lo);
            const uint32_t e0hi = __shfl_sync(0xffffffffu, p0, src_hi);
            const uint32_t e1hi = __shfl_sync(0xffffffffu, p1, src_hi);
            const uint32_t f0hi = __shfl_sync(0xffffffffu, p2, src_hi);
            const uint32_t f1hi = __shfl_sync(0xffffffffu, p3, src_hi);
            const uint32_t a0 = odd ? e1lo : e0lo;
            const uint32_t a1 = odd ? f1lo : f0lo;
            const uint32_t a2 = odd ? e1hi : e0hi;
            const uint32_t a3 = odd ? f1hi : f0hi;
            #pragma unroll
            for (int nt = 0; nt < 8; nt++) {
                uint32_t b0 = Vs[(ks * 8 + tig) * AT_STRIDE + nt * 8 + grp];
                uint32_t b1 = Vs[(ks * 8 + tig + 4) * AT_STRIDE + nt * 8 + grp];
                mma_tf32(o[nt][0], o[nt][1], o[nt][2], o[nt][3],
                         a0, a1, a2, a3, b0, b1);
            }
        }
        __syncthreads();   // all warps done with stage kt before its reuse
    }

    // ---- write normalized output to g_att [b, s, h*64 + d] ----
    const float inv0 = 1.0f / l0, inv1 = 1.0f / l1;
    const int b = bh >> 4, h = bh & 15;
    const int row0 = qbase + wrow + grp;
    float* o0 = g_att + (size_t)(b * SEQ + row0) * DMODEL + h * HD;
    float* o1 = g_att + (size_t)(b * SEQ + row0 + 8) * DMODEL + h * HD;
    #pragma unroll
    for (int nt = 0; nt < 8; nt++) {
        const int c = nt * 8 + tig * 2;
        *reinterpret_cast<float2*>(o0 + c) = make_float2(o[nt][0] * inv0, o[nt][1] * inv0);
        *reinterpret_cast<float2*>(o1 + c) = make_float2(o[nt][2] * inv1, o[nt][3] * inv1);
    }
}

// ===========================================================================
extern "C" void kernel_launch(void* const* d_in, const int* in_sizes, int n_in,
                              void* d_out, int out_size)
{
    const float* x     = (const float*)d_in[0];
    // d_in[1] is the causal mask; causality is implemented directly.
    const float* W_qkv = (const float*)d_in[2];
    const float* b_qkv = (const float*)d_in[3];
    const float* W_o   = (const float*)d_in[4];
    const float* b_o   = (const float*)d_in[5];
    float* out = (float*)d_out;

    cudaFuncSetAttribute(tc_gemm_kernel<0>,
                         cudaFuncAttributeMaxDynamicSharedMemorySize, TC_SMEM_BYTES);
    cudaFuncSetAttribute(tc_gemm_kernel<1>,
                         cudaFuncAttributeMaxDynamicSharedMemorySize, TC_SMEM_BYTES);
    cudaFuncSetAttribute(attn_tc_kernel,
                         cudaFuncAttributeMaxDynamicSharedMemorySize, AT_SMEM_BYTES);

    float* wqkv_t; cudaGetSymbolAddress((void**)&wqkv_t, g_wqkv_t);
    float* wo_t;   cudaGetSymbolAddress((void**)&wo_t, g_wo_t);
    float* att;    cudaGetSymbolAddress((void**)&att, g_att);

    transpose_kernel<<<dim3(N_QKV / 32, GK / 32), dim3(32, 8)>>>(W_qkv, wqkv_t, GK, N_QKV);
    transpose_kernel<<<dim3(DMODEL / 32, GK / 32), dim3(32, 8)>>>(W_o, wo_t, GK, DMODEL);

    tc_gemm_kernel<0><<<dim3(N_QKV / 128, (BATCH * SEQ) / 128), 256, TC_SMEM_BYTES>>>(
        x, wqkv_t, b_qkv, nullptr);
    attn_tc_kernel<<<(SEQ / 128) * BH, 256, AT_SMEM_BYTES>>>();
    tc_gemm_kernel<1><<<dim3(DMODEL / 128, (BATCH * SEQ) / 128), 256, TC_SMEM_BYTES>>>(
        att, wo_t, b_o, out);
}

// round 9
// speedup vs baseline: 4.6157x; 1.0002x over previous
#include <cuda_runtime.h>
#include <cstdint>

#define BATCH 2
#define SEQ 2048
#define DMODEL 1024
#define NH 16
#define HD 64
#define BH (BATCH * NH)
#define N_QKV (3 * DMODEL)
#define GK 1024

// Scratch (allocation-free). All tf32-bit buffers are uint32.
__device__ uint32_t g_q[BH * SEQ * HD];
__device__ uint32_t g_k[BH * SEQ * HD];
__device__ uint32_t g_v[BH * SEQ * HD];
__device__ uint32_t g_att[BATCH * SEQ * DMODEL];   // attn output, tf32 bits
__device__ uint32_t g_xt[BATCH * SEQ * GK];        // X converted to tf32 bits
__device__ uint32_t g_wqkv_t[N_QKV * GK];          // [N=3072, K=1024] tf32 bits
__device__ uint32_t g_wo_t[DMODEL * GK];           // [N=1024, K=1024] tf32 bits

__device__ __forceinline__ uint32_t f2tf32(float f) {
    uint32_t u;
    asm("cvt.rna.tf32.f32 %0, %1;" : "=r"(u) : "f"(f));
    return u;
}

__device__ __forceinline__ void mma_tf32(
    float& c0, float& c1, float& c2, float& c3,
    uint32_t a0, uint32_t a1, uint32_t a2, uint32_t a3,
    uint32_t b0, uint32_t b1)
{
    asm volatile(
        "mma.sync.aligned.m16n8k8.row.col.f32.tf32.tf32.f32 "
        "{%0,%1,%2,%3}, {%4,%5,%6,%7}, {%8,%9}, {%0,%1,%2,%3};"
        : "+f"(c0), "+f"(c1), "+f"(c2), "+f"(c3)
        : "r"(a0), "r"(a1), "r"(a2), "r"(a3), "r"(b0), "r"(b1));
}

__device__ __forceinline__ void cp_async16(uint32_t smem_addr, const void* gptr) {
    asm volatile("cp.async.cg.shared.global [%0], [%1], 16;"
                 :: "r"(smem_addr), "l"(gptr) : "memory");
}
#define CP_COMMIT() asm volatile("cp.async.commit_group;" ::: "memory")
#define CP_WAIT(n)  asm volatile("cp.async.wait_group %0;" :: "n"(n) : "memory")

// ===========================================================================
// Transpose+convert: out[c][r] = tf32(in[r][c]), in is R x C row-major fp32
// ===========================================================================
__global__ void transpose_tf32_kernel(const float* __restrict__ in,
                                      uint32_t* __restrict__ out, int R, int C)
{
    __shared__ float t[32][33];
    int c0 = blockIdx.x * 32, r0 = blockIdx.y * 32;
    int x = threadIdx.x, y = threadIdx.y;  // block (32, 8)
    #pragma unroll
    for (int i = 0; i < 32; i += 8)
        t[y + i][x] = in[(size_t)(r0 + y + i) * C + c0 + x];
    __syncthreads();
    #pragma unroll
    for (int i = 0; i < 32; i += 8)
        out[(size_t)(c0 + y + i) * R + r0 + x] = f2tf32(t[x][y + i]);
}

// ===========================================================================
// Elementwise convert: fp32 -> tf32 bits, vectorized
// ===========================================================================
__global__ void convert_x_kernel(const float* __restrict__ in,
                                 uint32_t* __restrict__ out)
{
    const int i = (blockIdx.x * 256 + threadIdx.x) * 4;
    float4 v = *reinterpret_cast<const float4*>(in + i);
    uint4 u = make_uint4(f2tf32(v.x), f2tf32(v.y), f2tf32(v.z), f2tf32(v.w));
    *reinterpret_cast<uint4*>(out + i) = u;
}

// ===========================================================================
// tf32 mma.sync GEMM, cp.async double-buffered, operands pre-converted.
// C[4096, N] = A @ Bt^T + bias.  CTA 128x128, 8 warps, warp m32 x n64.
// EPI 0: scatter q/k/v (tf32 bits).  EPI 1: fp32 write.
// ===========================================================================
#define KC 32
#define NKC (GK / KC)
#define ROWSTRIDE 36
#define STAGE_U32 (128 * ROWSTRIDE)             // one operand, one stage
#define TC_SMEM_BYTES (4 * STAGE_U32 * 4)       // A0,B0,A1,B1 = 73728 B

template<int EPI>
__global__ __launch_bounds__(256, 2) void tc_gemm_kernel(
    const uint32_t* __restrict__ A, const uint32_t* __restrict__ Bt,
    const float* __restrict__ bias, float* __restrict__ C)
{
    extern __shared__ uint32_t sm[];
    uint32_t smb;
    asm("{ .reg .u64 t; cvta.to.shared.u64 t, %1; cvt.u32.u64 %0, t; }"
        : "=r"(smb) : "l"(sm));

    const int tid = threadIdx.x;
    const int wid = tid >> 5, lane = tid & 31;
    const int grp = lane >> 2, tig = lane & 3;
    const int wm = wid >> 1, wn = wid & 1;
    const int m0 = blockIdx.y * 128;
    const int n0 = blockIdx.x * 128;

    const uint32_t* Ag = A + (size_t)m0 * GK;
    const uint32_t* Bg = Bt + (size_t)n0 * GK;

    // per-thread cp.async coords: 4 chunks of 16B per operand per k-chunk
    const int lr = tid >> 3;            // row 0..31 (x4 -> 128 rows)
    const int lc = (tid & 7) * 4;       // word col 0,4,...,28

    float acc[2][8][4];
    #pragma unroll
    for (int i = 0; i < 2; i++)
        #pragma unroll
        for (int j = 0; j < 8; j++)
            #pragma unroll
            for (int q = 0; q < 4; q++) acc[i][j][q] = 0.0f;

    // prologue: chunk 0 -> stage 0
    {
        const uint32_t asm0 = smb;
        const uint32_t bsm0 = smb + STAGE_U32 * 4;
        #pragma unroll
        for (int i = 0; i < 4; i++) {
            const int r = lr + 32 * i;
            cp_async16(asm0 + (r * ROWSTRIDE + lc) * 4, Ag + (size_t)r * GK + lc);
            cp_async16(bsm0 + (r * ROWSTRIDE + lc) * 4, Bg + (size_t)r * GK + lc);
        }
        CP_COMMIT();
    }

    for (int kc = 0; kc < NKC; kc++) {
        if (kc + 1 < NKC) {
            const int st = (kc + 1) & 1;
            const uint32_t asmx = smb + (st * 2 * STAGE_U32) * 4;
            const uint32_t bsmx = asmx + STAGE_U32 * 4;
            const uint32_t* an = Ag + (kc + 1) * KC;
            const uint32_t* bn = Bg + (kc + 1) * KC;
            #pragma unroll
            for (int i = 0; i < 4; i++) {
                const int r = lr + 32 * i;
                cp_async16(asmx + (r * ROWSTRIDE + lc) * 4, an + (size_t)r * GK + lc);
                cp_async16(bsmx + (r * ROWSTRIDE + lc) * 4, bn + (size_t)r * GK + lc);
            }
            CP_COMMIT();
            CP_WAIT(1);
        } else {
            CP_WAIT(0);
        }
        __syncthreads();   // stage kc resident

        const uint32_t* As = sm + (kc & 1) * 2 * STAGE_U32;
        const uint32_t* Bs = As + STAGE_U32;

        #pragma unroll
        for (int ks = 0; ks < 4; ks++) {
            const int kof = ks * 8;
            uint32_t af[2][4];
            #pragma unroll
            for (int mt = 0; mt < 2; mt++) {
                const int ab = wm * 32 + mt * 16;
                af[mt][0] = As[(ab + grp) * ROWSTRIDE + kof + tig];
                af[mt][1] = As[(ab + grp + 8) * ROWSTRIDE + kof + tig];
                af[mt][2] = As[(ab + grp) * ROWSTRIDE + kof + tig + 4];
                af[mt][3] = As[(ab + grp + 8) * ROWSTRIDE + kof + tig + 4];
            }
            #pragma unroll
            for (int nt = 0; nt < 8; nt++) {
                const int nb = wn * 64 + nt * 8;
                uint32_t b0 = Bs[(nb + grp) * ROWSTRIDE + kof + tig];
                uint32_t b1 = Bs[(nb + grp) * ROWSTRIDE + kof + tig + 4];
                #pragma unroll
                for (int mt = 0; mt < 2; mt++)
                    mma_tf32(acc[mt][nt][0], acc[mt][nt][1],
                             acc[mt][nt][2], acc[mt][nt][3],
                             af[mt][0], af[mt][1], af[mt][2], af[mt][3],
                             b0, b1);
            }
        }
        __syncthreads();   // all warps done with stage kc before its overwrite
    }

    #pragma unroll
    for (int mt = 0; mt < 2; mt++) {
        #pragma unroll
        for (int half = 0; half < 2; half++) {
            const int m = m0 + wm * 32 + mt * 16 + grp + half * 8;
            #pragma unroll
            for (int nt = 0; nt < 8; nt++) {
                #pragma unroll
                for (int e = 0; e < 2; e++) {
                    const int n = n0 + wn * 64 + nt * 8 + tig * 2 + e;
                    const float v = acc[mt][nt][half * 2 + e] + __ldg(&bias[n]);
                    if (EPI == 0) {
                        const int b = m >> 11;
                        const int srow = m & (SEQ - 1);
                        const int h = n / 192;
                        const int r = n - h * 192;
                        const int which = r >> 6;
                        const int dd = r & 63;
                        const size_t idx =
                            ((size_t)(b * NH + h) * SEQ + srow) * HD + dd;
                        if (which == 0)      g_q[idx] = f2tf32(v * 0.125f);
                        else if (which == 1) g_k[idx] = f2tf32(v);
                        else                 g_v[idx] = f2tf32(v);
                    } else {
                        C[(size_t)m * DMODEL + n] = v;
                    }
                }
            }
        }
    }
}

// ===========================================================================
// Tensor-core causal flash attention (unchanged structure from round 8;
// epilogue now writes tf32 bits into g_att — bit-identical to the cvt the
// out-GEMM used to apply at load time).
// ===========================================================================
#define AT_STRIDE 68
#define AT_STAGE_WORDS (64 * AT_STRIDE)
#define AT_SMEM_BYTES (4 * AT_STAGE_WORDS * 4)

__global__ __launch_bounds__(256, 2) void attn_tc_kernel()
{
    extern __shared__ uint32_t sm[];
    uint32_t smb;
    asm("{ .reg .u64 t; cvta.to.shared.u64 t, %1; cvt.u32.u64 %0, t; }"
        : "=r"(smb) : "l"(sm));

    const int tid = threadIdx.x;
    const int wid = tid >> 5, lane = tid & 31;
    const int grp = lane >> 2, tig = lane & 3;
    const int bid = blockIdx.x;
    const int qt = (SEQ / 128 - 1) - (bid >> 5);   // heavy tiles first
    const int bh = bid & 31;
    const int qbase = qt * 128;
    const int wrow = wid * 16;

    const uint32_t* __restrict__ Qu = g_q + (size_t)bh * SEQ * HD + (size_t)(qbase + wrow) * HD;
    const uint32_t* __restrict__ Ku = g_k + (size_t)bh * SEQ * HD;
    const uint32_t* __restrict__ Vu = g_v + (size_t)bh * SEQ * HD;

    uint32_t aq[8][4];
    #pragma unroll
    for (int ks = 0; ks < 8; ks++) {
        aq[ks][0] = __ldg(&Qu[grp * HD + ks * 8 + tig]);
        aq[ks][1] = __ldg(&Qu[(grp + 8) * HD + ks * 8 + tig]);
        aq[ks][2] = __ldg(&Qu[grp * HD + ks * 8 + tig + 4]);
        aq[ks][3] = __ldg(&Qu[(grp + 8) * HD + ks * 8 + tig + 4]);
    }

    float o[8][4];
    #pragma unroll
    for (int nt = 0; nt < 8; nt++)
        #pragma unroll
        for (int q = 0; q < 4; q++) o[nt][q] = 0.0f;
    float m0r = -1e30f, m1r = -1e30f, l0 = 0.0f, l1 = 0.0f;

    const int nkt = 2 * qt + 2;

    const int cr = tid >> 2;
    const int cc = (tid & 3) * 16;

    {
        const uint32_t ksm = smb;
        const uint32_t vsm = ksm + AT_STAGE_WORDS * 4;
        #pragma unroll
        for (int i = 0; i < 4; i++) {
            cp_async16(ksm + (cr * AT_STRIDE + cc + i * 4) * 4, Ku + (size_t)cr * HD + cc + i * 4);
            cp_async16(vsm + (cr * AT_STRIDE + cc + i * 4) * 4, Vu + (size_t)cr * HD + cc + i * 4);
        }
        CP_COMMIT();
    }

    const int src_lo = (grp << 2) | (tig >> 1);
    const int src_hi = src_lo + 2;
    const bool odd = (tig & 1) != 0;

    for (int kt = 0; kt < nkt; kt++) {
        if (kt + 1 < nkt) {
            const int st = (kt + 1) & 1;
            const uint32_t ksm = smb + (st * 2 * AT_STAGE_WORDS) * 4;
            const uint32_t vsm = ksm + AT_STAGE_WORDS * 4;
            const uint32_t* kg = Ku + (size_t)(kt + 1) * 64 * HD;
            const uint32_t* vg = Vu + (size_t)(kt + 1) * 64 * HD;
            #pragma unroll
            for (int i = 0; i < 4; i++) {
                cp_async16(ksm + (cr * AT_STRIDE + cc + i * 4) * 4, kg + (size_t)cr * HD + cc + i * 4);
                cp_async16(vsm + (cr * AT_STRIDE + cc + i * 4) * 4, vg + (size_t)cr * HD + cc + i * 4);
            }
            CP_COMMIT();
            CP_WAIT(1);
        } else {
            CP_WAIT(0);
        }
        __syncthreads();

        const uint32_t* Ks = sm + (kt & 1) * 2 * AT_STAGE_WORDS;
        const uint32_t* Vs = Ks + AT_STAGE_WORDS;

        float s[8][4];
        #pragma unroll
        for (int nt = 0; nt < 8; nt++)
            #pragma unroll
            for (int q = 0; q < 4; q++) s[nt][q] = 0.0f;

        #pragma unroll
        for (int ks = 0; ks < 8; ks++) {
            #pragma unroll
            for (int nt = 0; nt < 8; nt++) {
                uint32_t b0 = Ks[(nt * 8 + grp) * AT_STRIDE + ks * 8 + tig];
                uint32_t b1 = Ks[(nt * 8 + grp) * AT_STRIDE + ks * 8 + tig + 4];
                mma_tf32(s[nt][0], s[nt][1], s[nt][2], s[nt][3],
                         aq[ks][0], aq[ks][1], aq[ks][2], aq[ks][3], b0, b1);
            }
        }

        if (kt >= 2 * qt) {
            const int row0 = qbase + wrow + grp;
            const int colb = kt * 64 + tig * 2;
            #pragma unroll
            for (int nt = 0; nt < 8; nt++) {
                const int c = colb + nt * 8;
                if (c > row0)         s[nt][0] = -1e30f;
                if (c + 1 > row0)     s[nt][1] = -1e30f;
                if (c > row0 + 8)     s[nt][2] = -1e30f;
                if (c + 1 > row0 + 8) s[nt][3] = -1e30f;
            }
        }

        float rm0 = -1e30f, rm1 = -1e30f;
        #pragma unroll
        for (int nt = 0; nt < 8; nt++) {
            rm0 = fmaxf(rm0, fmaxf(s[nt][0], s[nt][1]));
            rm1 = fmaxf(rm1, fmaxf(s[nt][2], s[nt][3]));
        }
        rm0 = fmaxf(rm0, __shfl_xor_sync(0xffffffffu, rm0, 1));
        rm0 = fmaxf(rm0, __shfl_xor_sync(0xffffffffu, rm0, 2));
        rm1 = fmaxf(rm1, __shfl_xor_sync(0xffffffffu, rm1, 1));
        rm1 = fmaxf(rm1, __shfl_xor_sync(0xffffffffu, rm1, 2));

        const float mn0 = fmaxf(m0r, rm0), mn1 = fmaxf(m1r, rm1);
        const float cr0 = __expf(m0r - mn0), cr1 = __expf(m1r - mn1);
        float rs0 = 0.0f, rs1 = 0.0f;
        #pragma unroll
        for (int nt = 0; nt < 8; nt++) {
            s[nt][0] = __expf(s[nt][0] - mn0);
            s[nt][1] = __expf(s[nt][1] - mn0);
            s[nt][2] = __expf(s[nt][2] - mn1);
            s[nt][3] = __expf(s[nt][3] - mn1);
            rs0 += s[nt][0] + s[nt][1];
            rs1 += s[nt][2] + s[nt][3];
        }
        rs0 += __shfl_xor_sync(0xffffffffu, rs0, 1);
        rs0 += __shfl_xor_sync(0xffffffffu, rs0, 2);
        rs1 += __shfl_xor_sync(0xffffffffu, rs1, 1);
        rs1 += __shfl_xor_sync(0xffffffffu, rs1, 2);
        l0 = l0 * cr0 + rs0;  m0r = mn0;
        l1 = l1 * cr1 + rs1;  m1r = mn1;
        #pragma unroll
        for (int nt = 0; nt < 8; nt++) {
            o[nt][0] *= cr0; o[nt][1] *= cr0;
            o[nt][2] *= cr1; o[nt][3] *= cr1;
        }

        #pragma unroll
        for (int ks = 0; ks < 8; ks++) {
            const uint32_t p0 = f2tf32(s[ks][0]);
            const uint32_t p1 = f2tf32(s[ks][1]);
            const uint32_t p2 = f2tf32(s[ks][2]);
            const uint32_t p3 = f2tf32(s[ks][3]);
            const uint32_t e0lo = __shfl_sync(0xffffffffu, p0, src_lo);
            const uint32_t e1lo = __shfl_sync(0xffffffffu, p1, src_lo);
            const uint32_t f0lo = __shfl_sync(0xffffffffu, p2, src_lo);
            const uint32_t f1lo = __shfl_sync(0xffffffffu, p3, src_lo);
            const uint32_t e0hi = __shfl_sync(0xffffffffu, p0, src_hi);
            const uint32_t e1hi = __shfl_sync(0xffffffffu, p1, src_hi);
            const uint32_t f0hi = __shfl_sync(0xffffffffu, p2, src_hi);
            const uint32_t f1hi = __shfl_sync(0xffffffffu, p3, src_hi);
            const uint32_t a0 = odd ? e1lo : e0lo;
            const uint32_t a1 = odd ? f1lo : f0lo;
            const uint32_t a2 = odd ? e1hi : e0hi;
            const uint32_t a3 = odd ? f1hi : f0hi;
            #pragma unroll
            for (int nt = 0; nt < 8; nt++) {
                uint32_t b0 = Vs[(ks * 8 + tig) * AT_STRIDE + nt * 8 + grp];
                uint32_t b1 = Vs[(ks * 8 + tig + 4) * AT_STRIDE + nt * 8 + grp];
                mma_tf32(o[nt][0], o[nt][1], o[nt][2], o[nt][3],
                         a0, a1, a2, a3, b0, b1);
            }
        }
        __syncthreads();
    }

    // ---- write normalized output as tf32 bits to g_att [b, s, h*64 + d] ----
    const float inv0 = 1.0f / l0, inv1 = 1.0f / l1;
    const int b = bh >> 4, h = bh & 15;
    const int row0 = qbase + wrow + grp;
    uint32_t* o0 = g_att + (size_t)(b * SEQ + row0) * DMODEL + h * HD;
    uint32_t* o1 = g_att + (size_t)(b * SEQ + row0 + 8) * DMODEL + h * HD;
    #pragma unroll
    for (int nt = 0; nt < 8; nt++) {
        const int c = nt * 8 + tig * 2;
        *reinterpret_cast<uint2*>(o0 + c) =
            make_uint2(f2tf32(o[nt][0] * inv0), f2tf32(o[nt][1] * inv0));
        *reinterpret_cast<uint2*>(o1 + c) =
            make_uint2(f2tf32(o[nt][2] * inv1), f2tf32(o[nt][3] * inv1));
    }
}

// ===========================================================================
extern "C" void kernel_launch(void* const* d_in, const int* in_sizes, int n_in,
                              void* d_out, int out_size)
{
    const float* x     = (const float*)d_in[0];
    // d_in[1] is the causal mask; causality is implemented directly.
    const float* W_qkv = (const float*)d_in[2];
    const float* b_qkv = (const float*)d_in[3];
    const float* W_o   = (const float*)d_in[4];
    const float* b_o   = (const float*)d_in[5];
    float* out = (float*)d_out;

    cudaFuncSetAttribute(tc_gemm_kernel<0>,
                         cudaFuncAttributeMaxDynamicSharedMemorySize, TC_SMEM_BYTES);
    cudaFuncSetAttribute(tc_gemm_kernel<1>,
                         cudaFuncAttributeMaxDynamicSharedMemorySize, TC_SMEM_BYTES);
    cudaFuncSetAttribute(attn_tc_kernel,
                         cudaFuncAttributeMaxDynamicSharedMemorySize, AT_SMEM_BYTES);

    uint32_t* xt;     cudaGetSymbolAddress((void**)&xt, g_xt);
    uint32_t* wqkv_t; cudaGetSymbolAddress((void**)&wqkv_t, g_wqkv_t);
    uint32_t* wo_t;   cudaGetSymbolAddress((void**)&wo_t, g_wo_t);
    uint32_t* att;    cudaGetSymbolAddress((void**)&att, g_att);

    transpose_tf32_kernel<<<dim3(N_QKV / 32, GK / 32), dim3(32, 8)>>>(W_qkv, wqkv_t, GK, N_QKV);
    transpose_tf32_kernel<<<dim3(DMODEL / 32, GK / 32), dim3(32, 8)>>>(W_o, wo_t, GK, DMODEL);
    convert_x_kernel<<<(BATCH * SEQ * GK) / (256 * 4), 256>>>(x, xt);

    tc_gemm_kernel<0><<<dim3(N_QKV / 128, (BATCH * SEQ) / 128), 256, TC_SMEM_BYTES>>>(
        xt, wqkv_t, b_qkv, nullptr);
    attn_tc_kernel<<<(SEQ / 128) * BH, 256, AT_SMEM_BYTES>>>();
    tc_gemm_kernel<1><<<dim3(DMODEL / 128, (BATCH * SEQ) / 128), 256, TC_SMEM_BYTES>>>(
        att, wo_t, b_o, out);
}

// round 10
// speedup vs baseline: 7.2999x; 1.5815x over previous
#include <cuda_runtime.h>
#include <cuda_fp16.h>
#include <cstdint>

#define BATCH 2
#define SEQ 2048
#define DMODEL 1024
#define NH 16
#define HD 64
#define BH (BATCH * NH)
#define N_QKV (3 * DMODEL)
#define GK 1024

// Scratch (allocation-free). All operand buffers are fp16.
__device__ __half g_q[BH * SEQ * HD];          // [bh][s][d], pre-scaled by 0.125
__device__ __half g_k[BH * SEQ * HD];          // [bh][s][d]
__device__ __half g_v[BH * HD * SEQ];          // TRANSPOSED: [bh][d][s]
__device__ __half g_att[BATCH * SEQ * DMODEL]; // attn output
__device__ __half g_xt[BATCH * SEQ * GK];      // X converted
__device__ __half g_wqkv_t[N_QKV * GK];        // [N=3072][K=1024]
__device__ __half g_wo_t[DMODEL * GK];         // [N=1024][K=1024]

__device__ __forceinline__ uint32_t pack_h2(float lo, float hi) {
    __half2 h = __floats2half2_rn(lo, hi);
    return *reinterpret_cast<uint32_t*>(&h);
}

__device__ __forceinline__ void mma_f16(
    float& c0, float& c1, float& c2, float& c3,
    uint32_t a0, uint32_t a1, uint32_t a2, uint32_t a3,
    uint32_t b0, uint32_t b1)
{
    asm volatile(
        "mma.sync.aligned.m16n8k16.row.col.f32.f16.f16.f32 "
        "{%0,%1,%2,%3}, {%4,%5,%6,%7}, {%8,%9}, {%0,%1,%2,%3};"
        : "+f"(c0), "+f"(c1), "+f"(c2), "+f"(c3)
        : "r"(a0), "r"(a1), "r"(a2), "r"(a3), "r"(b0), "r"(b1));
}

__device__ __forceinline__ void cp_async16(uint32_t smem_addr, const void* gptr) {
    asm volatile("cp.async.cg.shared.global [%0], [%1], 16;"
                 :: "r"(smem_addr), "l"(gptr) : "memory");
}
#define CP_COMMIT() asm volatile("cp.async.commit_group;" ::: "memory")
#define CP_WAIT(n)  asm volatile("cp.async.wait_group %0;" :: "n"(n) : "memory")

// ===========================================================================
// Transpose+convert: out[c][r] = h(in[r][c]), in is R x C row-major fp32
// ===========================================================================
__global__ void transpose_h_kernel(const float* __restrict__ in,
                                   __half* __restrict__ out, int R, int C)
{
    __shared__ float t[32][33];
    int c0 = blockIdx.x * 32, r0 = blockIdx.y * 32;
    int x = threadIdx.x, y = threadIdx.y;  // block (32, 8)
    #pragma unroll
    for (int i = 0; i < 32; i += 8)
        t[y + i][x] = in[(size_t)(r0 + y + i) * C + c0 + x];
    __syncthreads();
    #pragma unroll
    for (int i = 0; i < 32; i += 8)
        out[(size_t)(c0 + y + i) * R + r0 + x] = __float2half_rn(t[x][y + i]);
}

// ===========================================================================
// Elementwise convert fp32 -> fp16, vectorized
// ===========================================================================
__global__ void convert_x_kernel(const float* __restrict__ in,
                                 __half* __restrict__ out)
{
    const int i = (blockIdx.x * 256 + threadIdx.x) * 4;
    float4 v = *reinterpret_cast<const float4*>(in + i);
    uint2 u;
    u.x = pack_h2(v.x, v.y);
    u.y = pack_h2(v.z, v.w);
    *reinterpret_cast<uint2*>(out + i) = u;
}

// ===========================================================================
// fp16 mma.sync GEMM, cp.async double-buffered, KC=64.
// C[4096, N] = A @ Bt^T + bias.  CTA 128x128, 8 warps (4M x 2N), warp m32 x n64.
// EPI 0: scatter q/k (and v transposed) as fp16.  EPI 1: fp32 write.
// ===========================================================================
#define KCH 64
#define NKCH (GK / KCH)                  // 16
#define RS_H 72                          // smem row stride in halfs
#define STAGE_H (128 * RS_H)             // halfs per operand per stage
#define STAGE_BYTES_G (STAGE_H * 2)      // 18432
#define STAGE_U32_G (STAGE_H / 2)        // 4608
#define TC_SMEM_BYTES (4 * STAGE_BYTES_G) // A0,B0,A1,B1 = 73728

template<int EPI>
__global__ __launch_bounds__(256, 2) void tc_gemm_kernel(
    const __half* __restrict__ A, const __half* __restrict__ Bt,
    const float* __restrict__ bias, float* __restrict__ C)
{
    extern __shared__ uint32_t sm[];
    uint32_t smb;
    asm("{ .reg .u64 t; cvta.to.shared.u64 t, %1; cvt.u32.u64 %0, t; }"
        : "=r"(smb) : "l"(sm));

    const int tid = threadIdx.x;
    const int wid = tid >> 5, lane = tid & 31;
    const int grp = lane >> 2, tig = lane & 3;
    const int wm = wid >> 1, wn = wid & 1;
    const int m0 = blockIdx.y * 128;
    const int n0 = blockIdx.x * 128;

    const __half* Ag = A + (size_t)m0 * GK;
    const __half* Bg = Bt + (size_t)n0 * GK;

    // cp.async coords: 128 rows x 128B per operand per chunk; 4x16B per thread
    const int lr = tid >> 1;            // row 0..127
    const int lcb = (tid & 1) * 4;      // chunk base 0 or 4 (8-half chunks)

    float acc[2][8][4];
    #pragma unroll
    for (int i = 0; i < 2; i++)
        #pragma unroll
        for (int j = 0; j < 8; j++)
            #pragma unroll
            for (int q = 0; q < 4; q++) acc[i][j][q] = 0.0f;

    // prologue: chunk 0 -> stage 0
    {
        const uint32_t asm0 = smb;
        const uint32_t bsm0 = smb + STAGE_BYTES_G;
        #pragma unroll
        for (int i = 0; i < 4; i++) {
            const int c = lcb + i;
            cp_async16(asm0 + (lr * RS_H + c * 8) * 2, Ag + (size_t)lr * GK + c * 8);
            cp_async16(bsm0 + (lr * RS_H + c * 8) * 2, Bg + (size_t)lr * GK + c * 8);
        }
        CP_COMMIT();
    }

    for (int kc = 0; kc < NKCH; kc++) {
        if (kc + 1 < NKCH) {
            const int st = (kc + 1) & 1;
            const uint32_t asmx = smb + st * 2 * STAGE_BYTES_G;
            const uint32_t bsmx = asmx + STAGE_BYTES_G;
            const __half* an = Ag + (kc + 1) * KCH;
            const __half* bn = Bg + (kc + 1) * KCH;
            #pragma unroll
            for (int i = 0; i < 4; i++) {
                const int c = lcb + i;
                cp_async16(asmx + (lr * RS_H + c * 8) * 2, an + (size_t)lr * GK + c * 8);
                cp_async16(bsmx + (lr * RS_H + c * 8) * 2, bn + (size_t)lr * GK + c * 8);
            }
            CP_COMMIT();
            CP_WAIT(1);
        } else {
            CP_WAIT(0);
        }
        __syncthreads();

        const uint32_t* As32 = sm + (kc & 1) * 2 * STAGE_U32_G;
        const uint32_t* Bs32 = As32 + STAGE_U32_G;

        #pragma unroll
        for (int ks = 0; ks < 4; ks++) {          // 4 x k16 per KC=64
            const int kof = ks * 8;               // u32 offset (16 halfs)
            uint32_t af[2][4];
            #pragma unroll
            for (int mt = 0; mt < 2; mt++) {
                const int ab = wm * 32 + mt * 16;
                af[mt][0] = As32[(ab + grp) * 36 + kof + tig];
                af[mt][1] = As32[(ab + grp + 8) * 36 + kof + tig];
                af[mt][2] = As32[(ab + grp) * 36 + kof + tig + 4];
                af[mt][3] = As32[(ab + grp + 8) * 36 + kof + tig + 4];
            }
            #pragma unroll
            for (int nt = 0; nt < 8; nt++) {
                const int nb = wn * 64 + nt * 8;
                uint32_t b0 = Bs32[(nb + grp) * 36 + kof + tig];
                uint32_t b1 = Bs32[(nb + grp) * 36 + kof + tig + 4];
                #pragma unroll
                for (int mt = 0; mt < 2; mt++)
                    mma_f16(acc[mt][nt][0], acc[mt][nt][1],
                            acc[mt][nt][2], acc[mt][nt][3],
                            af[mt][0], af[mt][1], af[mt][2], af[mt][3],
                            b0, b1);
            }
        }
        __syncthreads();
    }

    #pragma unroll
    for (int mt = 0; mt < 2; mt++) {
        #pragma unroll
        for (int half = 0; half < 2; half++) {
            const int m = m0 + wm * 32 + mt * 16 + grp + half * 8;
            #pragma unroll
            for (int nt = 0; nt < 8; nt++) {
                #pragma unroll
                for (int e = 0; e < 2; e++) {
                    const int n = n0 + wn * 64 + nt * 8 + tig * 2 + e;
                    const float v = acc[mt][nt][half * 2 + e] + __ldg(&bias[n]);
                    if (EPI == 0) {
                        const int b = m >> 11;
                        const int srow = m & (SEQ - 1);
                        const int h = n / 192;
                        const int r = n - h * 192;
                        const int which = r >> 6;
                        const int dd = r & 63;
                        const int bh = b * NH + h;
                        if (which == 0)
                            g_q[((size_t)bh * SEQ + srow) * HD + dd] =
                                __float2half_rn(v * 0.125f);
                        else if (which == 1)
                            g_k[((size_t)bh * SEQ + srow) * HD + dd] = __float2half_rn(v);
                        else
                            g_v[((size_t)bh * HD + dd) * SEQ + srow] = __float2half_rn(v);
                    } else {
                        C[(size_t)m * DMODEL + n] = v;
                    }
                }
            }
        }
    }
}

// ===========================================================================
// fp16 tensor-core causal flash attention, cp.async double-buffered K/V^T.
// CTA: 128 q-rows x 64-key tiles, 8 warps (warp m16 x n64).
// P stays in registers: S C-frag packs directly into PV A-frag (no shuffles).
// Grid: 1-D 512, LPT order.
// ===========================================================================
#define RS_A 72                            // smem row stride in halfs
#define AT_STAGE_H (64 * RS_A)             // halfs per operand tile
#define AT_STAGE_BYTES (AT_STAGE_H * 2)    // 9216
#define AT_STAGE_U32 (AT_STAGE_H / 2)      // 2304
#define AT_SMEM_BYTES (4 * AT_STAGE_BYTES) // K0,V0,K1,V1 = 36864

__global__ __launch_bounds__(256, 2) void attn_tc_kernel()
{
    extern __shared__ uint32_t sm[];
    uint32_t smb;
    asm("{ .reg .u64 t; cvta.to.shared.u64 t, %1; cvt.u32.u64 %0, t; }"
        : "=r"(smb) : "l"(sm));

    const int tid = threadIdx.x;
    const int wid = tid >> 5, lane = tid & 31;
    const int grp = lane >> 2, tig = lane & 3;
    const int bid = blockIdx.x;
    const int qt = (SEQ / 128 - 1) - (bid >> 5);   // heavy tiles first
    const int bh = bid & 31;
    const int qbase = qt * 128;
    const int wrow = wid * 16;

    const __half* __restrict__ Qu = g_q + ((size_t)bh * SEQ + qbase + wrow) * HD;
    const __half* __restrict__ Ku = g_k + (size_t)bh * SEQ * HD;
    const __half* __restrict__ Vu = g_v + (size_t)bh * HD * SEQ;   // [d][s]

    // ---- Q fragments straight from global (fp16, pre-scaled) ----
    uint32_t aq[4][4];
    #pragma unroll
    for (int kb = 0; kb < 4; kb++) {
        aq[kb][0] = *reinterpret_cast<const uint32_t*>(Qu + grp * HD + kb * 16 + 2 * tig);
        aq[kb][1] = *reinterpret_cast<const uint32_t*>(Qu + (grp + 8) * HD + kb * 16 + 2 * tig);
        aq[kb][2] = *reinterpret_cast<const uint32_t*>(Qu + grp * HD + kb * 16 + 8 + 2 * tig);
        aq[kb][3] = *reinterpret_cast<const uint32_t*>(Qu + (grp + 8) * HD + kb * 16 + 8 + 2 * tig);
    }

    float o[8][4];
    #pragma unroll
    for (int nt = 0; nt < 8; nt++)
        #pragma unroll
        for (int q = 0; q < 4; q++) o[nt][q] = 0.0f;
    float m0r = -1e30f, m1r = -1e30f, l0 = 0.0f, l1 = 0.0f;

    const int nkt = 2 * qt + 2;

    // cp.async coords: 64 rows x 128B per operand; 2x16B per thread per operand
    const int cr = tid >> 2;            // row 0..63
    const int ca = tid & 3;             // chunks ca and ca+4

    // prologue: tile 0 -> stage 0
    {
        const uint32_t ksm = smb;
        const uint32_t vsm = ksm + AT_STAGE_BYTES;
        #pragma unroll
        for (int i = 0; i < 2; i++) {
            const int c = ca + i * 4;
            cp_async16(ksm + (cr * RS_A + c * 8) * 2, Ku + (size_t)cr * HD + c * 8);
            cp_async16(vsm + (cr * RS_A + c * 8) * 2, Vu + (size_t)cr * SEQ + c * 8);
        }
        CP_COMMIT();
    }

    for (int kt = 0; kt < nkt; kt++) {
        if (kt + 1 < nkt) {
            const int st = (kt + 1) & 1;
            const uint32_t ksm = smb + st * 2 * AT_STAGE_BYTES;
            const uint32_t vsm = ksm + AT_STAGE_BYTES;
            const __half* kg = Ku + (size_t)(kt + 1) * 64 * HD;
            const __half* vg = Vu + (size_t)(kt + 1) * 64;        // col offset in [d][s]
            #pragma unroll
            for (int i = 0; i < 2; i++) {
                const int c = ca + i * 4;
                cp_async16(ksm + (cr * RS_A + c * 8) * 2, kg + (size_t)cr * HD + c * 8);
                cp_async16(vsm + (cr * RS_A + c * 8) * 2, vg + (size_t)cr * SEQ + c * 8);
            }
            CP_COMMIT();
            CP_WAIT(1);
        } else {
            CP_WAIT(0);
        }
        __syncthreads();   // tile kt resident for all warps

        const uint32_t* Ks32 = sm + (kt & 1) * 2 * AT_STAGE_U32;
        const uint32_t* Vs32 = Ks32 + AT_STAGE_U32;

        // ---- S = Q K^T : 4 k16-blocks x 8 n-tiles ----
        float s[8][4];
        #pragma unroll
        for (int nt = 0; nt < 8; nt++)
            #pragma unroll
            for (int q = 0; q < 4; q++) s[nt][q] = 0.0f;

        #pragma unroll
        for (int kb = 0; kb < 4; kb++) {
            #pragma unroll
            for (int nt = 0; nt < 8; nt++) {
                uint32_t b0 = Ks32[(nt * 8 + grp) * 36 + kb * 8 + tig];
                uint32_t b1 = Ks32[(nt * 8 + grp) * 36 + kb * 8 + tig + 4];
                mma_f16(s[nt][0], s[nt][1], s[nt][2], s[nt][3],
                        aq[kb][0], aq[kb][1], aq[kb][2], aq[kb][3], b0, b1);
            }
        }

        // ---- causal mask (last two tiles only) ----
        if (kt >= 2 * qt) {
            const int row0 = qbase + wrow + grp;
            const int colb = kt * 64 + tig * 2;
            #pragma unroll
            for (int nt = 0; nt < 8; nt++) {
                const int c = colb + nt * 8;
                if (c > row0)         s[nt][0] = -1e30f;
                if (c + 1 > row0)     s[nt][1] = -1e30f;
                if (c > row0 + 8)     s[nt][2] = -1e30f;
                if (c + 1 > row0 + 8) s[nt][3] = -1e30f;
            }
        }

        // ---- online softmax (2 rows per thread, quad reduce) ----
        float rm0 = -1e30f, rm1 = -1e30f;
        #pragma unroll
        for (int nt = 0; nt < 8; nt++) {
            rm0 = fmaxf(rm0, fmaxf(s[nt][0], s[nt][1]));
            rm1 = fmaxf(rm1, fmaxf(s[nt][2], s[nt][3]));
        }
        rm0 = fmaxf(rm0, __shfl_xor_sync(0xffffffffu, rm0, 1));
        rm0 = fmaxf(rm0, __shfl_xor_sync(0xffffffffu, rm0, 2));
        rm1 = fmaxf(rm1, __shfl_xor_sync(0xffffffffu, rm1, 1));
        rm1 = fmaxf(rm1, __shfl_xor_sync(0xffffffffu, rm1, 2));

        const float mn0 = fmaxf(m0r, rm0), mn1 = fmaxf(m1r, rm1);
        const float cr0 = __expf(m0r - mn0), cr1 = __expf(m1r - mn1);
        float rs0 = 0.0f, rs1 = 0.0f;
        #pragma unroll
        for (int nt = 0; nt < 8; nt++) {
            s[nt][0] = __expf(s[nt][0] - mn0);
            s[nt][1] = __expf(s[nt][1] - mn0);
            s[nt][2] = __expf(s[nt][2] - mn1);
            s[nt][3] = __expf(s[nt][3] - mn1);
            rs0 += s[nt][0] + s[nt][1];
            rs1 += s[nt][2] + s[nt][3];
        }
        rs0 += __shfl_xor_sync(0xffffffffu, rs0, 1);
        rs0 += __shfl_xor_sync(0xffffffffu, rs0, 2);
        rs1 += __shfl_xor_sync(0xffffffffu, rs1, 1);
        rs1 += __shfl_xor_sync(0xffffffffu, rs1, 2);
        l0 = l0 * cr0 + rs0;  m0r = mn0;
        l1 = l1 * cr1 + rs1;  m1r = mn1;
        #pragma unroll
        for (int nt = 0; nt < 8; nt++) {
            o[nt][0] *= cr0; o[nt][1] *= cr0;
            o[nt][2] *= cr1; o[nt][3] *= cr1;
        }

        // ---- O += P V : C-frag packs directly into A-frag (no shuffles) ----
        #pragma unroll
        for (int kb = 0; kb < 4; kb++) {
            const uint32_t a0 = pack_h2(s[2 * kb][0], s[2 * kb][1]);
            const uint32_t a1 = pack_h2(s[2 * kb][2], s[2 * kb][3]);
            const uint32_t a2 = pack_h2(s[2 * kb + 1][0], s[2 * kb + 1][1]);
            const uint32_t a3 = pack_h2(s[2 * kb + 1][2], s[2 * kb + 1][3]);
            #pragma unroll
            for (int nt = 0; nt < 8; nt++) {
                uint32_t b0 = Vs32[(nt * 8 + grp) * 36 + kb * 8 + tig];
                uint32_t b1 = Vs32[(nt * 8 + grp) * 36 + kb * 8 + tig + 4];
                mma_f16(o[nt][0], o[nt][1], o[nt][2], o[nt][3],
                        a0, a1, a2, a3, b0, b1);
            }
        }
        __syncthreads();   // all warps done with stage kt before its reuse
    }

    // ---- write normalized output (fp16) to g_att [b, s, h*64 + d] ----
    const float inv0 = 1.0f / l0, inv1 = 1.0f / l1;
    const int b = bh >> 4, h = bh & 15;
    const int row0 = qbase + wrow + grp;
    __half* o0 = g_att + (size_t)(b * SEQ + row0) * DMODEL + h * HD;
    __half* o1 = g_att + (size_t)(b * SEQ + row0 + 8) * DMODEL + h * HD;
    #pragma unroll
    for (int nt = 0; nt < 8; nt++) {
        const int c = nt * 8 + tig * 2;
        *reinterpret_cast<uint32_t*>(o0 + c) = pack_h2(o[nt][0] * inv0, o[nt][1] * inv0);
        *reinterpret_cast<uint32_t*>(o1 + c) = pack_h2(o[nt][2] * inv1, o[nt][3] * inv1);
    }
}

// ===========================================================================
extern "C" void kernel_launch(void* const* d_in, const int* in_sizes, int n_in,
                              void* d_out, int out_size)
{
    const float* x     = (const float*)d_in[0];
    // d_in[1] is the causal mask; causality is implemented directly.
    const float* W_qkv = (const float*)d_in[2];
    const float* b_qkv = (const float*)d_in[3];
    const float* W_o   = (const float*)d_in[4];
    const float* b_o   = (const float*)d_in[5];
    float* out = (float*)d_out;

    cudaFuncSetAttribute(tc_gemm_kernel<0>,
                         cudaFuncAttributeMaxDynamicSharedMemorySize, TC_SMEM_BYTES);
    cudaFuncSetAttribute(tc_gemm_kernel<1>,
                         cudaFuncAttributeMaxDynamicSharedMemorySize, TC_SMEM_BYTES);
    cudaFuncSetAttribute(attn_tc_kernel,
                         cudaFuncAttributeMaxDynamicSharedMemorySize, AT_SMEM_BYTES);

    __half* xt;     cudaGetSymbolAddress((void**)&xt, g_xt);
    __half* wqkv_t; cudaGetSymbolAddress((void**)&wqkv_t, g_wqkv_t);
    __half* wo_t;   cudaGetSymbolAddress((void**)&wo_t, g_wo_t);
    __half* att;    cudaGetSymbolAddress((void**)&att, g_att);

    transpose_h_kernel<<<dim3(N_QKV / 32, GK / 32), dim3(32, 8)>>>(W_qkv, wqkv_t, GK, N_QKV);
    transpose_h_kernel<<<dim3(DMODEL / 32, GK / 32), dim3(32, 8)>>>(W_o, wo_t, GK, DMODEL);
    convert_x_kernel<<<(BATCH * SEQ * GK) / (256 * 4), 256>>>(x, xt);

    tc_gemm_kernel<0><<<dim3(N_QKV / 128, (BATCH * SEQ) / 128), 256, TC_SMEM_BYTES>>>(
        xt, wqkv_t, b_qkv, nullptr);
    attn_tc_kernel<<<(SEQ / 128) * BH, 256, AT_SMEM_BYTES>>>();
    tc_gemm_kernel<1><<<dim3(DMODEL / 128, (BATCH * SEQ) / 128), 256, TC_SMEM_BYTES>>>(
        att, wo_t, b_o, out);
}

// round 11
// speedup vs baseline: 7.7367x; 1.0598x over previous
#include <cuda_runtime.h>
#include <cuda_fp16.h>
#include <cstdint>

#define BATCH 2
#define SEQ 2048
#define DMODEL 1024
#define NH 16
#define HD 64
#define BH (BATCH * NH)
#define N_QKV (3 * DMODEL)
#define GK 1024

// Scratch (allocation-free). All operand buffers are fp16.
__device__ __half g_q[BH * SEQ * HD];          // [bh][s][d], pre-scaled by 0.125
__device__ __half g_k[BH * SEQ * HD];          // [bh][s][d]
__device__ __half g_v[BH * HD * SEQ];          // TRANSPOSED: [bh][d][s]
__device__ __half g_att[BATCH * SEQ * DMODEL]; // attn output
__device__ __half g_xt[BATCH * SEQ * GK];      // X converted
__device__ __half g_wqkv_t[N_QKV * GK];        // [N=3072][K=1024]
__device__ __half g_wo_t[DMODEL * GK];         // [N=1024][K=1024]

__device__ __forceinline__ uint32_t pack_h2(float lo, float hi) {
    __half2 h = __floats2half2_rn(lo, hi);
    return *reinterpret_cast<uint32_t*>(&h);
}

__device__ __forceinline__ void mma_f16(
    float& c0, float& c1, float& c2, float& c3,
    uint32_t a0, uint32_t a1, uint32_t a2, uint32_t a3,
    uint32_t b0, uint32_t b1)
{
    asm volatile(
        "mma.sync.aligned.m16n8k16.row.col.f32.f16.f16.f32 "
        "{%0,%1,%2,%3}, {%4,%5,%6,%7}, {%8,%9}, {%0,%1,%2,%3};"
        : "+f"(c0), "+f"(c1), "+f"(c2), "+f"(c3)
        : "r"(a0), "r"(a1), "r"(a2), "r"(a3), "r"(b0), "r"(b1));
}

__device__ __forceinline__ void ldsm_x4(
    uint32_t& r0, uint32_t& r1, uint32_t& r2, uint32_t& r3, uint32_t saddr)
{
    asm volatile(
        "ldmatrix.sync.aligned.m8n8.x4.shared.b16 {%0,%1,%2,%3}, [%4];"
        : "=r"(r0), "=r"(r1), "=r"(r2), "=r"(r3) : "r"(saddr));
}

__device__ __forceinline__ void cp_async16(uint32_t smem_addr, const void* gptr) {
    asm volatile("cp.async.cg.shared.global [%0], [%1], 16;"
                 :: "r"(smem_addr), "l"(gptr) : "memory");
}
#define CP_COMMIT() asm volatile("cp.async.commit_group;" ::: "memory")
#define CP_WAIT(n)  asm volatile("cp.async.wait_group %0;" :: "n"(n) : "memory")

// ===========================================================================
// Transpose+convert: out[c][r] = h(in[r][c]), in is R x C row-major fp32
// ===========================================================================
__global__ void transpose_h_kernel(const float* __restrict__ in,
                                   __half* __restrict__ out, int R, int C)
{
    __shared__ float t[32][33];
    int c0 = blockIdx.x * 32, r0 = blockIdx.y * 32;
    int x = threadIdx.x, y = threadIdx.y;  // block (32, 8)
    #pragma unroll
    for (int i = 0; i < 32; i += 8)
        t[y + i][x] = in[(size_t)(r0 + y + i) * C + c0 + x];
    __syncthreads();
    #pragma unroll
    for (int i = 0; i < 32; i += 8)
        out[(size_t)(c0 + y + i) * R + r0 + x] = __float2half_rn(t[x][y + i]);
}

// ===========================================================================
// Elementwise convert fp32 -> fp16, vectorized
// ===========================================================================
__global__ void convert_x_kernel(const float* __restrict__ in,
                                 __half* __restrict__ out)
{
    const int i = (blockIdx.x * 256 + threadIdx.x) * 4;
    float4 v = *reinterpret_cast<const float4*>(in + i);
    uint2 u;
    u.x = pack_h2(v.x, v.y);
    u.y = pack_h2(v.z, v.w);
    *reinterpret_cast<uint2*>(out + i) = u;
}

// ===========================================================================
// fp16 mma.sync GEMM, cp.async double-buffered, KC=64, ldmatrix fragments.
// C[4096, N] = A @ Bt^T + bias.  CTA 128x128, 8 warps (4M x 2N), warp m32 x n64.
// EPI 0: scatter q/k (and v transposed) as fp16.  EPI 1: fp32 write.
// ===========================================================================
#define KCH 64
#define NKCH (GK / KCH)                  // 16
#define RS_H 72                          // smem row stride in halfs
#define STAGE_H (128 * RS_H)             // halfs per operand per stage
#define STAGE_BYTES_G (STAGE_H * 2)      // 18432
#define TC_SMEM_BYTES (4 * STAGE_BYTES_G) // A0,B0,A1,B1 = 73728

template<int EPI>
__global__ __launch_bounds__(256, 2) void tc_gemm_kernel(
    const __half* __restrict__ A, const __half* __restrict__ Bt,
    const float* __restrict__ bias, float* __restrict__ C)
{
    extern __shared__ uint32_t sm[];
    uint32_t smb;
    asm("{ .reg .u64 t; cvta.to.shared.u64 t, %1; cvt.u32.u64 %0, t; }"
        : "=r"(smb) : "l"(sm));

    const int tid = threadIdx.x;
    const int wid = tid >> 5, lane = tid & 31;
    const int grp = lane >> 2, tig = lane & 3;
    const int wm = wid >> 1, wn = wid & 1;
    const int m0 = blockIdx.y * 128;
    const int n0 = blockIdx.x * 128;

    const __half* Ag = A + (size_t)m0 * GK;
    const __half* Bg = Bt + (size_t)n0 * GK;

    // ldmatrix per-lane row/col mapping
    const int lt = lane >> 3, le = lane & 7;
    const int rA = le + (lt & 1) * 8;          // A: tiles (m8, m8+8) x (k0-7, k8-15)
    const int cA = (lt >> 1) * 8;
    const int rB = le + (lt >> 1) * 8;         // B: tiles (n8, n8+8) x (k0-7, k8-15)
    const int cB = (lt & 1) * 8;

    // cp.async coords: 128 rows x 128B per operand per chunk; 4x16B per thread
    const int lr = tid >> 1;            // row 0..127
    const int lcb = (tid & 1) * 4;      // chunk base 0 or 4 (8-half chunks)

    float acc[2][8][4];
    #pragma unroll
    for (int i = 0; i < 2; i++)
        #pragma unroll
        for (int j = 0; j < 8; j++)
            #pragma unroll
            for (int q = 0; q < 4; q++) acc[i][j][q] = 0.0f;

    // prologue: chunk 0 -> stage 0
    {
        const uint32_t asm0 = smb;
        const uint32_t bsm0 = smb + STAGE_BYTES_G;
        #pragma unroll
        for (int i = 0; i < 4; i++) {
            const int c = lcb + i;
            cp_async16(asm0 + (lr * RS_H + c * 8) * 2, Ag + (size_t)lr * GK + c * 8);
            cp_async16(bsm0 + (lr * RS_H + c * 8) * 2, Bg + (size_t)lr * GK + c * 8);
        }
        CP_COMMIT();
    }

    for (int kc = 0; kc < NKCH; kc++) {
        if (kc + 1 < NKCH) {
            const int st = (kc + 1) & 1;
            const uint32_t asmx = smb + st * 2 * STAGE_BYTES_G;
            const uint32_t bsmx = asmx + STAGE_BYTES_G;
            const __half* an = Ag + (kc + 1) * KCH;
            const __half* bn = Bg + (kc + 1) * KCH;
            #pragma unroll
            for (int i = 0; i < 4; i++) {
                const int c = lcb + i;
                cp_async16(asmx + (lr * RS_H + c * 8) * 2, an + (size_t)lr * GK + c * 8);
                cp_async16(bsmx + (lr * RS_H + c * 8) * 2, bn + (size_t)lr * GK + c * 8);
            }
            CP_COMMIT();
            CP_WAIT(1);
        } else {
            CP_WAIT(0);
        }
        __syncthreads();

        const uint32_t abase = smb + (kc & 1) * 2 * STAGE_BYTES_G;
        const uint32_t bbase = abase + STAGE_BYTES_G;

        #pragma unroll
        for (int ks = 0; ks < 4; ks++) {          // 4 x k16 per KC=64
            const int kh = ks * 16;               // half offset
            uint32_t af[2][4];
            #pragma unroll
            for (int mt = 0; mt < 2; mt++)
                ldsm_x4(af[mt][0], af[mt][1], af[mt][2], af[mt][3],
                        abase + ((wm * 32 + mt * 16 + rA) * RS_H + kh + cA) * 2);
            uint32_t bf[4][4];
            #pragma unroll
            for (int p = 0; p < 4; p++)
                ldsm_x4(bf[p][0], bf[p][1], bf[p][2], bf[p][3],
                        bbase + ((wn * 64 + p * 16 + rB) * RS_H + kh + cB) * 2);
            #pragma unroll
            for (int nt = 0; nt < 8; nt++) {
                const uint32_t b0 = bf[nt >> 1][(nt & 1) * 2];
                const uint32_t b1 = bf[nt >> 1][(nt & 1) * 2 + 1];
                #pragma unroll
                for (int mt = 0; mt < 2; mt++)
                    mma_f16(acc[mt][nt][0], acc[mt][nt][1],
                            acc[mt][nt][2], acc[mt][nt][3],
                            af[mt][0], af[mt][1], af[mt][2], af[mt][3],
                            b0, b1);
            }
        }
        __syncthreads();
    }

    #pragma unroll
    for (int mt = 0; mt < 2; mt++) {
        #pragma unroll
        for (int half = 0; half < 2; half++) {
            const int m = m0 + wm * 32 + mt * 16 + grp + half * 8;
            #pragma unroll
            for (int nt = 0; nt < 8; nt++) {
                #pragma unroll
                for (int e = 0; e < 2; e++) {
                    const int n = n0 + wn * 64 + nt * 8 + tig * 2 + e;
                    const float v = acc[mt][nt][half * 2 + e] + __ldg(&bias[n]);
                    if (EPI == 0) {
                        const int b = m >> 11;
                        const int srow = m & (SEQ - 1);
                        const int h = n / 192;
                        const int r = n - h * 192;
                        const int which = r >> 6;
                        const int dd = r & 63;
                        const int bh = b * NH + h;
                        if (which == 0)
                            g_q[((size_t)bh * SEQ + srow) * HD + dd] =
                                __float2half_rn(v * 0.125f);
                        else if (which == 1)
                            g_k[((size_t)bh * SEQ + srow) * HD + dd] = __float2half_rn(v);
                        else
                            g_v[((size_t)bh * HD + dd) * SEQ + srow] = __float2half_rn(v);
                    } else {
                        C[(size_t)m * DMODEL + n] = v;
                    }
                }
            }
        }
    }
}

// ===========================================================================
// fp16 tensor-core causal flash attention, cp.async double-buffered K/V^T,
// ldmatrix fragments.  CTA: 128 q-rows x 64-key tiles, 8 warps (warp m16xn64).
// P stays in registers: S C-frag packs directly into PV A-frag.
// Grid: 1-D 512, LPT order.
// ===========================================================================
#define RS_A 72                            // smem row stride in halfs
#define AT_STAGE_H (64 * RS_A)             // halfs per operand tile
#define AT_STAGE_BYTES (AT_STAGE_H * 2)    // 9216
#define AT_SMEM_BYTES (4 * AT_STAGE_BYTES) // K0,V0,K1,V1 = 36864

__global__ __launch_bounds__(256, 2) void attn_tc_kernel()
{
    extern __shared__ uint32_t sm[];
    uint32_t smb;
    asm("{ .reg .u64 t; cvta.to.shared.u64 t, %1; cvt.u32.u64 %0, t; }"
        : "=r"(smb) : "l"(sm));

    const int tid = threadIdx.x;
    const int wid = tid >> 5, lane = tid & 31;
    const int grp = lane >> 2, tig = lane & 3;
    const int bid = blockIdx.x;
    const int qt = (SEQ / 128 - 1) - (bid >> 5);   // heavy tiles first
    const int bh = bid & 31;
    const int qbase = qt * 128;
    const int wrow = wid * 16;

    const __half* __restrict__ Qu = g_q + ((size_t)bh * SEQ + qbase + wrow) * HD;
    const __half* __restrict__ Ku = g_k + (size_t)bh * SEQ * HD;
    const __half* __restrict__ Vu = g_v + (size_t)bh * HD * SEQ;   // [d][s]

    // ldmatrix B-side lane mapping
    const int lt = lane >> 3, le = lane & 7;
    const int rB = le + (lt >> 1) * 8;
    const int cB = (lt & 1) * 8;

    // ---- Q fragments straight from global (fp16, pre-scaled) ----
    uint32_t aq[4][4];
    #pragma unroll
    for (int kb = 0; kb < 4; kb++) {
        aq[kb][0] = *reinterpret_cast<const uint32_t*>(Qu + grp * HD + kb * 16 + 2 * tig);
        aq[kb][1] = *reinterpret_cast<const uint32_t*>(Qu + (grp + 8) * HD + kb * 16 + 2 * tig);
        aq[kb][2] = *reinterpret_cast<const uint32_t*>(Qu + grp * HD + kb * 16 + 8 + 2 * tig);
        aq[kb][3] = *reinterpret_cast<const uint32_t*>(Qu + (grp + 8) * HD + kb * 16 + 8 + 2 * tig);
    }

    float o[8][4];
    #pragma unroll
    for (int nt = 0; nt < 8; nt++)
        #pragma unroll
        for (int q = 0; q < 4; q++) o[nt][q] = 0.0f;
    float m0r = -1e30f, m1r = -1e30f, l0 = 0.0f, l1 = 0.0f;

    const int nkt = 2 * qt + 2;

    // cp.async coords: 64 rows x 128B per operand; 2x16B per thread per operand
    const int cr = tid >> 2;            // row 0..63
    const int ca = tid & 3;             // chunks ca and ca+4

    // prologue: tile 0 -> stage 0
    {
        const uint32_t ksm = smb;
        const uint32_t vsm = ksm + AT_STAGE_BYTES;
        #pragma unroll
        for (int i = 0; i < 2; i++) {
            const int c = ca + i * 4;
            cp_async16(ksm + (cr * RS_A + c * 8) * 2, Ku + (size_t)cr * HD + c * 8);
            cp_async16(vsm + (cr * RS_A + c * 8) * 2, Vu + (size_t)cr * SEQ + c * 8);
        }
        CP_COMMIT();
    }

    for (int kt = 0; kt < nkt; kt++) {
        if (kt + 1 < nkt) {
            const int st = (kt + 1) & 1;
            const uint32_t ksm = smb + st * 2 * AT_STAGE_BYTES;
            const uint32_t vsm = ksm + AT_STAGE_BYTES;
            const __half* kg = Ku + (size_t)(kt + 1) * 64 * HD;
            const __half* vg = Vu + (size_t)(kt + 1) * 64;        // col offset in [d][s]
            #pragma unroll
            for (int i = 0; i < 2; i++) {
                const int c = ca + i * 4;
                cp_async16(ksm + (cr * RS_A + c * 8) * 2, kg + (size_t)cr * HD + c * 8);
                cp_async16(vsm + (cr * RS_A + c * 8) * 2, vg + (size_t)cr * SEQ + c * 8);
            }
            CP_COMMIT();
            CP_WAIT(1);
        } else {
            CP_WAIT(0);
        }
        __syncthreads();   // tile kt resident for all warps

        const uint32_t kbase_b = smb + (kt & 1) * 2 * AT_STAGE_BYTES;
        const uint32_t vbase_b = kbase_b + AT_STAGE_BYTES;

        // ---- S = Q K^T : 4 k16-blocks x 8 n-tiles ----
        float s[8][4];
        #pragma unroll
        for (int nt = 0; nt < 8; nt++)
            #pragma unroll
            for (int q = 0; q < 4; q++) s[nt][q] = 0.0f;

        #pragma unroll
        for (int kb = 0; kb < 4; kb++) {
            uint32_t kf[4][4];
            #pragma unroll
            for (int p = 0; p < 4; p++)
                ldsm_x4(kf[p][0], kf[p][1], kf[p][2], kf[p][3],
                        kbase_b + ((p * 16 + rB) * RS_A + kb * 16 + cB) * 2);
            #pragma unroll
            for (int nt = 0; nt < 8; nt++) {
                const uint32_t b0 = kf[nt >> 1][(nt & 1) * 2];
                const uint32_t b1 = kf[nt >> 1][(nt & 1) * 2 + 1];
                mma_f16(s[nt][0], s[nt][1], s[nt][2], s[nt][3],
                        aq[kb][0], aq[kb][1], aq[kb][2], aq[kb][3], b0, b1);
            }
        }

        // ---- causal mask (last two tiles only) ----
        if (kt >= 2 * qt) {
            const int row0 = qbase + wrow + grp;
            const int colb = kt * 64 + tig * 2;
            #pragma unroll
            for (int nt = 0; nt < 8; nt++) {
                const int c = colb + nt * 8;
                if (c > row0)         s[nt][0] = -1e30f;
                if (c + 1 > row0)     s[nt][1] = -1e30f;
                if (c > row0 + 8)     s[nt][2] = -1e30f;
                if (c + 1 > row0 + 8) s[nt][3] = -1e30f;
            }
        }

        // ---- online softmax (2 rows per thread, quad reduce) ----
        float rm0 = -1e30f, rm1 = -1e30f;
        #pragma unroll
        for (int nt = 0; nt < 8; nt++) {
            rm0 = fmaxf(rm0, fmaxf(s[nt][0], s[nt][1]));
            rm1 = fmaxf(rm1, fmaxf(s[nt][2], s[nt][3]));
        }
        rm0 = fmaxf(rm0, __shfl_xor_sync(0xffffffffu, rm0, 1));
        rm0 = fmaxf(rm0, __shfl_xor_sync(0xffffffffu, rm0, 2));
        rm1 = fmaxf(rm1, __shfl_xor_sync(0xffffffffu, rm1, 1));
        rm1 = fmaxf(rm1, __shfl_xor_sync(0xffffffffu, rm1, 2));

        const float mn0 = fmaxf(m0r, rm0), mn1 = fmaxf(m1r, rm1);
        const float cr0 = __expf(m0r - mn0), cr1 = __expf(m1r - mn1);
        float rs0 = 0.0f, rs1 = 0.0f;
        #pragma unroll
        for (int nt = 0; nt < 8; nt++) {
            s[nt][0] = __expf(s[nt][0] - mn0);
            s[nt][1] = __expf(s[nt][1] - mn0);
            s[nt][2] = __expf(s[nt][2] - mn1);
            s[nt][3] = __expf(s[nt][3] - mn1);
            rs0 += s[nt][0] + s[nt][1];
            rs1 += s[nt][2] + s[nt][3];
        }
        rs0 += __shfl_xor_sync(0xffffffffu, rs0, 1);
        rs0 += __shfl_xor_sync(0xffffffffu, rs0, 2);
        rs1 += __shfl_xor_sync(0xffffffffu, rs1, 1);
        rs1 += __shfl_xor_sync(0xffffffffu, rs1, 2);
        l0 = l0 * cr0 + rs0;  m0r = mn0;
        l1 = l1 * cr1 + rs1;  m1r = mn1;
        #pragma unroll
        for (int nt = 0; nt < 8; nt++) {
            o[nt][0] *= cr0; o[nt][1] *= cr0;
            o[nt][2] *= cr1; o[nt][3] *= cr1;
        }

        // ---- O += P V : C-frag packs directly into A-frag ----
        #pragma unroll
        for (int kb = 0; kb < 4; kb++) {
            const uint32_t a0 = pack_h2(s[2 * kb][0], s[2 * kb][1]);
            const uint32_t a1 = pack_h2(s[2 * kb][2], s[2 * kb][3]);
            const uint32_t a2 = pack_h2(s[2 * kb + 1][0], s[2 * kb + 1][1]);
            const uint32_t a3 = pack_h2(s[2 * kb + 1][2], s[2 * kb + 1][3]);
            uint32_t vf[4][4];
            #pragma unroll
            for (int p = 0; p < 4; p++)
                ldsm_x4(vf[p][0], vf[p][1], vf[p][2], vf[p][3],
                        vbase_b + ((p * 16 + rB) * RS_A + kb * 16 + cB) * 2);
            #pragma unroll
            for (int nt = 0; nt < 8; nt++) {
                const uint32_t b0 = vf[nt >> 1][(nt & 1) * 2];
                const uint32_t b1 = vf[nt >> 1][(nt & 1) * 2 + 1];
                mma_f16(o[nt][0], o[nt][1], o[nt][2], o[nt][3],
                        a0, a1, a2, a3, b0, b1);
            }
        }
        __syncthreads();   // all warps done with stage kt before its reuse
    }

    // ---- write normalized output (fp16) to g_att [b, s, h*64 + d] ----
    const float inv0 = 1.0f / l0, inv1 = 1.0f / l1;
    const int b = bh >> 4, h = bh & 15;
    const int row0 = qbase + wrow + grp;
    __half* o0 = g_att + (size_t)(b * SEQ + row0) * DMODEL + h * HD;
    __half* o1 = g_att + (size_t)(b * SEQ + row0 + 8) * DMODEL + h * HD;
    #pragma unroll
    for (int nt = 0; nt < 8; nt++) {
        const int c = nt * 8 + tig * 2;
        *reinterpret_cast<uint32_t*>(o0 + c) = pack_h2(o[nt][0] * inv0, o[nt][1] * inv0);
        *reinterpret_cast<uint32_t*>(o1 + c) = pack_h2(o[nt][2] * inv1, o[nt][3] * inv1);
    }
}

// ===========================================================================
extern "C" void kernel_launch(void* const* d_in, const int* in_sizes, int n_in,
                              void* d_out, int out_size)
{
    const float* x     = (const float*)d_in[0];
    // d_in[1] is the causal mask; causality is implemented directly.
    const float* W_qkv = (const float*)d_in[2];
    const float* b_qkv = (const float*)d_in[3];
    const float* W_o   = (const float*)d_in[4];
    const float* b_o   = (const float*)d_in[5];
    float* out = (float*)d_out;

    cudaFuncSetAttribute(tc_gemm_kernel<0>,
                         cudaFuncAttributeMaxDynamicSharedMemorySize, TC_SMEM_BYTES);
    cudaFuncSetAttribute(tc_gemm_kernel<1>,
                         cudaFuncAttributeMaxDynamicSharedMemorySize, TC_SMEM_BYTES);
    cudaFuncSetAttribute(attn_tc_kernel,
                         cudaFuncAttributeMaxDynamicSharedMemorySize, AT_SMEM_BYTES);

    __half* xt;     cudaGetSymbolAddress((void**)&xt, g_xt);
    __half* wqkv_t; cudaGetSymbolAddress((void**)&wqkv_t, g_wqkv_t);
    __half* wo_t;   cudaGetSymbolAddress((void**)&wo_t, g_wo_t);
    __half* att;    cudaGetSymbolAddress((void**)&att, g_att);

    transpose_h_kernel<<<dim3(N_QKV / 32, GK / 32), dim3(32, 8)>>>(W_qkv, wqkv_t, GK, N_QKV);
    transpose_h_kernel<<<dim3(DMODEL / 32, GK / 32), dim3(32, 8)>>>(W_o, wo_t, GK, DMODEL);
    convert_x_kernel<<<(BATCH * SEQ * GK) / (256 * 4), 256>>>(x, xt);

    tc_gemm_kernel<0><<<dim3(N_QKV / 128, (BATCH * SEQ) / 128), 256, TC_SMEM_BYTES>>>(
        xt, wqkv_t, b_qkv, nullptr);
    attn_tc_kernel<<<(SEQ / 128) * BH, 256, AT_SMEM_BYTES>>>();
    tc_gemm_kernel<1><<<dim3(DMODEL / 128, (BATCH * SEQ) / 128), 256, TC_SMEM_BYTES>>>(
        att, wo_t, b_o, out);
}

// round 12
// speedup vs baseline: 8.3721x; 1.0821x over previous
#include <cuda_runtime.h>
#include <cuda_fp16.h>
#include <cstdint>

#define BATCH 2
#define SEQ 2048
#define DMODEL 1024
#define NH 16
#define HD 64
#define BH (BATCH * NH)
#define N_QKV (3 * DMODEL)
#define GK 1024

// Scratch (allocation-free). All operand buffers are fp16.
__device__ __half g_q[BH * SEQ * HD];          // [bh][s][d], pre-scaled by 0.125
__device__ __half g_k[BH * SEQ * HD];          // [bh][s][d]
__device__ __half g_v[BH * HD * SEQ];          // TRANSPOSED: [bh][d][s]
__device__ __half g_att[BATCH * SEQ * DMODEL]; // attn output
__device__ __half g_xt[BATCH * SEQ * GK];      // X converted
__device__ __half g_wqkv_t[N_QKV * GK];        // [N=3072][K=1024]
__device__ __half g_wo_t[DMODEL * GK];         // [N=1024][K=1024]

__device__ __forceinline__ uint32_t pack_h2(float lo, float hi) {
    __half2 h = __floats2half2_rn(lo, hi);
    return *reinterpret_cast<uint32_t*>(&h);
}

__device__ __forceinline__ void mma_f16(
    float& c0, float& c1, float& c2, float& c3,
    uint32_t a0, uint32_t a1, uint32_t a2, uint32_t a3,
    uint32_t b0, uint32_t b1)
{
    asm volatile(
        "mma.sync.aligned.m16n8k16.row.col.f32.f16.f16.f32 "
        "{%0,%1,%2,%3}, {%4,%5,%6,%7}, {%8,%9}, {%0,%1,%2,%3};"
        : "+f"(c0), "+f"(c1), "+f"(c2), "+f"(c3)
        : "r"(a0), "r"(a1), "r"(a2), "r"(a3), "r"(b0), "r"(b1));
}

__device__ __forceinline__ void ldsm_x4(
    uint32_t& r0, uint32_t& r1, uint32_t& r2, uint32_t& r3, uint32_t saddr)
{
    asm volatile(
        "ldmatrix.sync.aligned.m8n8.x4.shared.b16 {%0,%1,%2,%3}, [%4];"
        : "=r"(r0), "=r"(r1), "=r"(r2), "=r"(r3) : "r"(saddr));
}

__device__ __forceinline__ void cp_async16(uint32_t smem_addr, const void* gptr) {
    asm volatile("cp.async.cg.shared.global [%0], [%1], 16;"
                 :: "r"(smem_addr), "l"(gptr) : "memory");
}
#define CP_COMMIT() asm volatile("cp.async.commit_group;" ::: "memory")
#define CP_WAIT(n)  asm volatile("cp.async.wait_group %0;" :: "n"(n) : "memory")

// ===========================================================================
// Transpose+convert: out[c][r] = h(in[r][c]), in is R x C row-major fp32
// ===========================================================================
__global__ void transpose_h_kernel(const float* __restrict__ in,
                                   __half* __restrict__ out, int R, int C)
{
    __shared__ float t[32][33];
    int c0 = blockIdx.x * 32, r0 = blockIdx.y * 32;
    int x = threadIdx.x, y = threadIdx.y;  // block (32, 8)
    #pragma unroll
    for (int i = 0; i < 32; i += 8)
        t[y + i][x] = in[(size_t)(r0 + y + i) * C + c0 + x];
    __syncthreads();
    #pragma unroll
    for (int i = 0; i < 32; i += 8)
        out[(size_t)(c0 + y + i) * R + r0 + x] = __float2half_rn(t[x][y + i]);
}

// ===========================================================================
// Elementwise convert fp32 -> fp16, vectorized
// ===========================================================================
__global__ void convert_x_kernel(const float* __restrict__ in,
                                 __half* __restrict__ out)
{
    const int i = (blockIdx.x * 256 + threadIdx.x) * 4;
    float4 v = *reinterpret_cast<const float4*>(in + i);
    uint2 u;
    u.x = pack_h2(v.x, v.y);
    u.y = pack_h2(v.z, v.w);
    *reinterpret_cast<uint2*>(out + i) = u;
}

// ===========================================================================
// fp16 mma.sync GEMM, 4-stage cp.async pipeline, KC=32, ldmatrix fragments.
// C[4096, N] = A @ Bt^T + bias.  CTA 128x128, 8 warps (4M x 2N), warp m32xn64.
// EPI 0: scatter q/k (and v transposed) as fp16.  EPI 1: fp32 write.
// ===========================================================================
#define KCH 32
#define NKCH (GK / KCH)                  // 32
#define NSTAGE 4
#define RS_H 40                          // smem row stride in halfs (32 + pad)
#define OP_BYTES (128 * RS_H * 2)        // 10240 per operand per stage
#define STAGE_BYTES_G (2 * OP_BYTES)     // 20480 (A then B)
#define TC_SMEM_BYTES (NSTAGE * STAGE_BYTES_G)  // 81920

template<int EPI>
__global__ __launch_bounds__(256, 2) void tc_gemm_kernel(
    const __half* __restrict__ A, const __half* __restrict__ Bt,
    const float* __restrict__ bias, float* __restrict__ C)
{
    extern __shared__ uint32_t sm[];
    uint32_t smb;
    asm("{ .reg .u64 t; cvta.to.shared.u64 t, %1; cvt.u32.u64 %0, t; }"
        : "=r"(smb) : "l"(sm));

    const int tid = threadIdx.x;
    const int wid = tid >> 5, lane = tid & 31;
    const int grp = lane >> 2, tig = lane & 3;
    const int wm = wid >> 1, wn = wid & 1;
    const int m0 = blockIdx.y * 128;
    const int n0 = blockIdx.x * 128;

    const __half* Ag = A + (size_t)m0 * GK;
    const __half* Bg = Bt + (size_t)n0 * GK;

    // ldmatrix per-lane row/col mapping
    const int lt = lane >> 3, le = lane & 7;
    const int rA = le + (lt & 1) * 8;          // A: tiles (m8, m8+8) x (k0-7, k8-15)
    const int cA = (lt >> 1) * 8;
    const int rB = le + (lt >> 1) * 8;         // B: tiles (n8, n8+8) x (k0-7, k8-15)
    const int cB = (lt & 1) * 8;

    // cp.async coords: 128 rows x 64B per operand per chunk; 2x16B per thread
    const int lr = tid >> 1;            // row 0..127
    const int lcb = (tid & 1) * 2;      // chunk base 0 or 2 (8-half chunks)

    float acc[2][8][4];
    #pragma unroll
    for (int i = 0; i < 2; i++)
        #pragma unroll
        for (int j = 0; j < 8; j++)
            #pragma unroll
            for (int q = 0; q < 4; q++) acc[i][j][q] = 0.0f;

    // prologue: chunks 0..NSTAGE-2 into stages 0..NSTAGE-2 (one group each)
    #pragma unroll
    for (int p = 0; p < NSTAGE - 1; p++) {
        const uint32_t asmp = smb + p * STAGE_BYTES_G;
        const uint32_t bsmp = asmp + OP_BYTES;
        const __half* ap = Ag + p * KCH;
        const __half* bp = Bg + p * KCH;
        #pragma unroll
        for (int i = 0; i < 2; i++) {
            const int c = lcb + i;
            cp_async16(asmp + (lr * RS_H + c * 8) * 2, ap + (size_t)lr * GK + c * 8);
            cp_async16(bsmp + (lr * RS_H + c * 8) * 2, bp + (size_t)lr * GK + c * 8);
        }
        CP_COMMIT();
    }

    for (int kc = 0; kc < NKCH; kc++) {
        // wait for chunk kc (3 groups lookahead while body; all at tail)
        if (kc < NKCH - NSTAGE + 1) { CP_WAIT(NSTAGE - 2); }
        else                        { CP_WAIT(0); }
        __syncthreads();   // all warps: chunk kc visible, compute kc-1 done

        // prefetch chunk kc+NSTAGE-1 into stage (kc-1)%NSTAGE (safe: barrier)
        if (kc + NSTAGE - 1 < NKCH) {
            const int st = (kc + NSTAGE - 1) % NSTAGE;
            const uint32_t asmx = smb + st * STAGE_BYTES_G;
            const uint32_t bsmx = asmx + OP_BYTES;
            const __half* an = Ag + (kc + NSTAGE - 1) * KCH;
            const __half* bn = Bg + (kc + NSTAGE - 1) * KCH;
            #pragma unroll
            for (int i = 0; i < 2; i++) {
                const int c = lcb + i;
                cp_async16(asmx + (lr * RS_H + c * 8) * 2, an + (size_t)lr * GK + c * 8);
                cp_async16(bsmx + (lr * RS_H + c * 8) * 2, bn + (size_t)lr * GK + c * 8);
            }
            CP_COMMIT();
        }

        const uint32_t abase = smb + (kc % NSTAGE) * STAGE_BYTES_G;
        const uint32_t bbase = abase + OP_BYTES;

        #pragma unroll
        for (int ks = 0; ks < 2; ks++) {          // 2 x k16 per KC=32
            const int kh = ks * 16;               // half offset
            uint32_t af[2][4];
            #pragma unroll
            for (int mt = 0; mt < 2; mt++)
                ldsm_x4(af[mt][0], af[mt][1], af[mt][2], af[mt][3],
                        abase + ((wm * 32 + mt * 16 + rA) * RS_H + kh + cA) * 2);
            uint32_t bf[4][4];
            #pragma unroll
            for (int p = 0; p < 4; p++)
                ldsm_x4(bf[p][0], bf[p][1], bf[p][2], bf[p][3],
                        bbase + ((wn * 64 + p * 16 + rB) * RS_H + kh + cB) * 2);
            #pragma unroll
            for (int nt = 0; nt < 8; nt++) {
                const uint32_t b0 = bf[nt >> 1][(nt & 1) * 2];
                const uint32_t b1 = bf[nt >> 1][(nt & 1) * 2 + 1];
                #pragma unroll
                for (int mt = 0; mt < 2; mt++)
                    mma_f16(acc[mt][nt][0], acc[mt][nt][1],
                            acc[mt][nt][2], acc[mt][nt][3],
                            af[mt][0], af[mt][1], af[mt][2], af[mt][3],
                            b0, b1);
            }
        }
    }

    #pragma unroll
    for (int mt = 0; mt < 2; mt++) {
        #pragma unroll
        for (int half = 0; half < 2; half++) {
            const int m = m0 + wm * 32 + mt * 16 + grp + half * 8;
            #pragma unroll
            for (int nt = 0; nt < 8; nt++) {
                #pragma unroll
                for (int e = 0; e < 2; e++) {
                    const int n = n0 + wn * 64 + nt * 8 + tig * 2 + e;
                    const float v = acc[mt][nt][half * 2 + e] + __ldg(&bias[n]);
                    if (EPI == 0) {
                        const int b = m >> 11;
                        const int srow = m & (SEQ - 1);
                        const int h = n / 192;
                        const int r = n - h * 192;
                        const int which = r >> 6;
                        const int dd = r & 63;
                        const int bh = b * NH + h;
                        if (which == 0)
                            g_q[((size_t)bh * SEQ + srow) * HD + dd] =
                                __float2half_rn(v * 0.125f);
                        else if (which == 1)
                            g_k[((size_t)bh * SEQ + srow) * HD + dd] = __float2half_rn(v);
                        else
                            g_v[((size_t)bh * HD + dd) * SEQ + srow] = __float2half_rn(v);
                    } else {
                        C[(size_t)m * DMODEL + n] = v;
                    }
                }
            }
        }
    }
}

// ===========================================================================
// fp16 tensor-core causal flash attention, cp.async double-buffered K/V^T,
// ldmatrix fragments.  (Unchanged from round 11 — protect the win.)
// ===========================================================================
#define RS_A 72                            // smem row stride in halfs
#define AT_STAGE_H (64 * RS_A)             // halfs per operand tile
#define AT_STAGE_BYTES (AT_STAGE_H * 2)    // 9216
#define AT_SMEM_BYTES (4 * AT_STAGE_BYTES) // K0,V0,K1,V1 = 36864

__global__ __launch_bounds__(256, 2) void attn_tc_kernel()
{
    extern __shared__ uint32_t sm[];
    uint32_t smb;
    asm("{ .reg .u64 t; cvta.to.shared.u64 t, %1; cvt.u32.u64 %0, t; }"
        : "=r"(smb) : "l"(sm));

    const int tid = threadIdx.x;
    const int wid = tid >> 5, lane = tid & 31;
    const int grp = lane >> 2, tig = lane & 3;
    const int bid = blockIdx.x;
    const int qt = (SEQ / 128 - 1) - (bid >> 5);   // heavy tiles first
    const int bh = bid & 31;
    const int qbase = qt * 128;
    const int wrow = wid * 16;

    const __half* __restrict__ Qu = g_q + ((size_t)bh * SEQ + qbase + wrow) * HD;
    const __half* __restrict__ Ku = g_k + (size_t)bh * SEQ * HD;
    const __half* __restrict__ Vu = g_v + (size_t)bh * HD * SEQ;   // [d][s]

    // ldmatrix B-side lane mapping
    const int lt = lane >> 3, le = lane & 7;
    const int rB = le + (lt >> 1) * 8;
    const int cB = (lt & 1) * 8;

    // ---- Q fragments straight from global (fp16, pre-scaled) ----
    uint32_t aq[4][4];
    #pragma unroll
    for (int kb = 0; kb < 4; kb++) {
        aq[kb][0] = *reinterpret_cast<const uint32_t*>(Qu + grp * HD + kb * 16 + 2 * tig);
        aq[kb][1] = *reinterpret_cast<const uint32_t*>(Qu + (grp + 8) * HD + kb * 16 + 2 * tig);
        aq[kb][2] = *reinterpret_cast<const uint32_t*>(Qu + grp * HD + kb * 16 + 8 + 2 * tig);
        aq[kb][3] = *reinterpret_cast<const uint32_t*>(Qu + (grp + 8) * HD + kb * 16 + 8 + 2 * tig);
    }

    float o[8][4];
    #pragma unroll
    for (int nt = 0; nt < 8; nt++)
        #pragma unroll
        for (int q = 0; q < 4; q++) o[nt][q] = 0.0f;
    float m0r = -1e30f, m1r = -1e30f, l0 = 0.0f, l1 = 0.0f;

    const int nkt = 2 * qt + 2;

    // cp.async coords: 64 rows x 128B per operand; 2x16B per thread per operand
    const int cr = tid >> 2;            // row 0..63
    const int ca = tid & 3;             // chunks ca and ca+4

    // prologue: tile 0 -> stage 0
    {
        const uint32_t ksm = smb;
        const uint32_t vsm = ksm + AT_STAGE_BYTES;
        #pragma unroll
        for (int i = 0; i < 2; i++) {
            const int c = ca + i * 4;
            cp_async16(ksm + (cr * RS_A + c * 8) * 2, Ku + (size_t)cr * HD + c * 8);
            cp_async16(vsm + (cr * RS_A + c * 8) * 2, Vu + (size_t)cr * SEQ + c * 8);
        }
        CP_COMMIT();
    }

    for (int kt = 0; kt < nkt; kt++) {
        if (kt + 1 < nkt) {
            const int st = (kt + 1) & 1;
            const uint32_t ksm = smb + st * 2 * AT_STAGE_BYTES;
            const uint32_t vsm = ksm + AT_STAGE_BYTES;
            const __half* kg = Ku + (size_t)(kt + 1) * 64 * HD;
            const __half* vg = Vu + (size_t)(kt + 1) * 64;        // col offset in [d][s]
            #pragma unroll
            for (int i = 0; i < 2; i++) {
                const int c = ca + i * 4;
                cp_async16(ksm + (cr * RS_A + c * 8) * 2, kg + (size_t)cr * HD + c * 8);
                cp_async16(vsm + (cr * RS_A + c * 8) * 2, vg + (size_t)cr * SEQ + c * 8);
            }
            CP_COMMIT();
            CP_WAIT(1);
        } else {
            CP_WAIT(0);
        }
        __syncthreads();   // tile kt resident for all warps

        const uint32_t kbase_b = smb + (kt & 1) * 2 * AT_STAGE_BYTES;
        const uint32_t vbase_b = kbase_b + AT_STAGE_BYTES;

        // ---- S = Q K^T : 4 k16-blocks x 8 n-tiles ----
        float s[8][4];
        #pragma unroll
        for (int nt = 0; nt < 8; nt++)
            #pragma unroll
            for (int q = 0; q < 4; q++) s[nt][q] = 0.0f;

        #pragma unroll
        for (int kb = 0; kb < 4; kb++) {
            uint32_t kf[4][4];
            #pragma unroll
            for (int p = 0; p < 4; p++)
                ldsm_x4(kf[p][0], kf[p][1], kf[p][2], kf[p][3],
                        kbase_b + ((p * 16 + rB) * RS_A + kb * 16 + cB) * 2);
            #pragma unroll
            for (int nt = 0; nt < 8; nt++) {
                const uint32_t b0 = kf[nt >> 1][(nt & 1) * 2];
                const uint32_t b1 = kf[nt >> 1][(nt & 1) * 2 + 1];
                mma_f16(s[nt][0], s[nt][1], s[nt][2], s[nt][3],
                        aq[kb][0], aq[kb][1], aq[kb][2], aq[kb][3], b0, b1);
            }
        }

        // ---- causal mask (last two tiles only) ----
        if (kt >= 2 * qt) {
            const int row0 = qbase + wrow + grp;
            const int colb = kt * 64 + tig * 2;
            #pragma unroll
            for (int nt = 0; nt < 8; nt++) {
                const int c = colb + nt * 8;
                if (c > row0)         s[nt][0] = -1e30f;
                if (c + 1 > row0)     s[nt][1] = -1e30f;
                if (c > row0 + 8)     s[nt][2] = -1e30f;
                if (c + 1 > row0 + 8) s[nt][3] = -1e30f;
            }
        }

        // ---- online softmax (2 rows per thread, quad reduce) ----
        float rm0 = -1e30f, rm1 = -1e30f;
        #pragma unroll
        for (int nt = 0; nt < 8; nt++) {
            rm0 = fmaxf(rm0, fmaxf(s[nt][0], s[nt][1]));
            rm1 = fmaxf(rm1, fmaxf(s[nt][2], s[nt][3]));
        }
        rm0 = fmaxf(rm0, __shfl_xor_sync(0xffffffffu, rm0, 1));
        rm0 = fmaxf(rm0, __shfl_xor_sync(0xffffffffu, rm0, 2));
        rm1 = fmaxf(rm1, __shfl_xor_sync(0xffffffffu, rm1, 1));
        rm1 = fmaxf(rm1, __shfl_xor_sync(0xffffffffu, rm1, 2));

        const float mn0 = fmaxf(m0r, rm0), mn1 = fmaxf(m1r, rm1);
        const float cr0 = __expf(m0r - mn0), cr1 = __expf(m1r - mn1);
        float rs0 = 0.0f, rs1 = 0.0f;
        #pragma unroll
        for (int nt = 0; nt < 8; nt++) {
            s[nt][0] = __expf(s[nt][0] - mn0);
            s[nt][1] = __expf(s[nt][1] - mn0);
            s[nt][2] = __expf(s[nt][2] - mn1);
            s[nt][3] = __expf(s[nt][3] - mn1);
            rs0 += s[nt][0] + s[nt][1];
            rs1 += s[nt][2] + s[nt][3];
        }
        rs0 += __shfl_xor_sync(0xffffffffu, rs0, 1);
        rs0 += __shfl_xor_sync(0xffffffffu, rs0, 2);
        rs1 += __shfl_xor_sync(0xffffffffu, rs1, 1);
        rs1 += __shfl_xor_sync(0xffffffffu, rs1, 2);
        l0 = l0 * cr0 + rs0;  m0r = mn0;
        l1 = l1 * cr1 + rs1;  m1r = mn1;
        #pragma unroll
        for (int nt = 0; nt < 8; nt++) {
            o[nt][0] *= cr0; o[nt][1] *= cr0;
            o[nt][2] *= cr1; o[nt][3] *= cr1;
        }

        // ---- O += P V : C-frag packs directly into A-frag ----
        #pragma unroll
        for (int kb = 0; kb < 4; kb++) {
            const uint32_t a0 = pack_h2(s[2 * kb][0], s[2 * kb][1]);
            const uint32_t a1 = pack_h2(s[2 * kb][2], s[2 * kb][3]);
            const uint32_t a2 = pack_h2(s[2 * kb + 1][0], s[2 * kb + 1][1]);
            const uint32_t a3 = pack_h2(s[2 * kb + 1][2], s[2 * kb + 1][3]);
            uint32_t vf[4][4];
            #pragma unroll
            for (int p = 0; p < 4; p++)
                ldsm_x4(vf[p][0], vf[p][1], vf[p][2], vf[p][3],
                        vbase_b + ((p * 16 + rB) * RS_A + kb * 16 + cB) * 2);
            #pragma unroll
            for (int nt = 0; nt < 8; nt++) {
                const uint32_t b0 = vf[nt >> 1][(nt & 1) * 2];
                const uint32_t b1 = vf[nt >> 1][(nt & 1) * 2 + 1];
                mma_f16(o[nt][0], o[nt][1], o[nt][2], o[nt][3],
                        a0, a1, a2, a3, b0, b1);
            }
        }
        __syncthreads();   // all warps done with stage kt before its reuse
    }

    // ---- write normalized output (fp16) to g_att [b, s, h*64 + d] ----
    const float inv0 = 1.0f / l0, inv1 = 1.0f / l1;
    const int b = bh >> 4, h = bh & 15;
    const int row0 = qbase + wrow + grp;
    __half* o0 = g_att + (size_t)(b * SEQ + row0) * DMODEL + h * HD;
    __half* o1 = g_att + (size_t)(b * SEQ + row0 + 8) * DMODEL + h * HD;
    #pragma unroll
    for (int nt = 0; nt < 8; nt++) {
        const int c = nt * 8 + tig * 2;
        *reinterpret_cast<uint32_t*>(o0 + c) = pack_h2(o[nt][0] * inv0, o[nt][1] * inv0);
        *reinterpret_cast<uint32_t*>(o1 + c) = pack_h2(o[nt][2] * inv1, o[nt][3] * inv1);
    }
}

// ===========================================================================
extern "C" void kernel_launch(void* const* d_in, const int* in_sizes, int n_in,
                              void* d_out, int out_size)
{
    const float* x     = (const float*)d_in[0];
    // d_in[1] is the causal mask; causality is implemented directly.
    const float* W_qkv = (const float*)d_in[2];
    const float* b_qkv = (const float*)d_in[3];
    const float* W_o   = (const float*)d_in[4];
    const float* b_o   = (const float*)d_in[5];
    float* out = (float*)d_out;

    cudaFuncSetAttribute(tc_gemm_kernel<0>,
                         cudaFuncAttributeMaxDynamicSharedMemorySize, TC_SMEM_BYTES);
    cudaFuncSetAttribute(tc_gemm_kernel<1>,
                         cudaFuncAttributeMaxDynamicSharedMemorySize, TC_SMEM_BYTES);
    cudaFuncSetAttribute(attn_tc_kernel,
                         cudaFuncAttributeMaxDynamicSharedMemorySize, AT_SMEM_BYTES);

    __half* xt;     cudaGetSymbolAddress((void**)&xt, g_xt);
    __half* wqkv_t; cudaGetSymbolAddress((void**)&wqkv_t, g_wqkv_t);
    __half* wo_t;   cudaGetSymbolAddress((void**)&wo_t, g_wo_t);
    __half* att;    cudaGetSymbolAddress((void**)&att, g_att);

    transpose_h_kernel<<<dim3(N_QKV / 32, GK / 32), dim3(32, 8)>>>(W_qkv, wqkv_t, GK, N_QKV);
    transpose_h_kernel<<<dim3(DMODEL / 32, GK / 32), dim3(32, 8)>>>(W_o, wo_t, GK, DMODEL);
    convert_x_kernel<<<(BATCH * SEQ * GK) / (256 * 4), 256>>>(x, xt);

    tc_gemm_kernel<0><<<dim3(N_QKV / 128, (BATCH * SEQ) / 128), 256, TC_SMEM_BYTES>>>(
        xt, wqkv_t, b_qkv, nullptr);
    attn_tc_kernel<<<(SEQ / 128) * BH, 256, AT_SMEM_BYTES>>>();
    tc_gemm_kernel<1><<<dim3(DMODEL / 128, (BATCH * SEQ) / 128), 256, TC_SMEM_BYTES>>>(
        att, wo_t, b_o, out);
}